// round 1
// baseline (speedup 1.0000x reference)
#include <cuda_runtime.h>
#include <cuda_bf16.h>
#include <cstdint>

// Problem constants (fixed by setup_inputs)
#define BATCH   16
#define NTOK    1569          // 1 + 8*196
#define DMODEL  768
#define NHEAD   12
#define DHEAD   64
#define NF      8             // windows per sequence
#define NWIN    196           // tokens per window
#define NKEY    197           // window keys (cls + 196)
#define MROWS   (BATCH * NTOK)      // 25104
#define QKVCOLS (3 * DMODEL)        // 2304

// Scratch (allocation-free rule: __device__ globals)
__device__ float g_qkv [ (size_t)MROWS * QKVCOLS ];   // 231 MB
__device__ float g_attn[ (size_t)MROWS * DMODEL  ];   // 77 MB

// ---------------------------------------------------------------------------
// SGEMM: C[M,N] = A[M,K] @ B[K,N] (+ bias). 128x128 tile, BK=8, 256 threads,
// 8x8 per-thread register tile. N, K multiples of 128/8; only M needs bounds.
// ---------------------------------------------------------------------------
__global__ __launch_bounds__(256) void sgemm_kernel(
    const float* __restrict__ A, const float* __restrict__ B,
    float* __restrict__ C, const float* __restrict__ bias,
    int M, int N, int K)
{
    __shared__ float As[8][128];   // transposed A tile
    __shared__ float Bs[8][128];

    const int tid  = threadIdx.x;
    const int row0 = blockIdx.y * 128;
    const int col0 = blockIdx.x * 128;
    const int tx = tid & 15;       // 0..15
    const int ty = tid >> 4;       // 0..15

    float acc[8][8];
    #pragma unroll
    for (int i = 0; i < 8; i++)
        #pragma unroll
        for (int j = 0; j < 8; j++) acc[i][j] = 0.f;

    const int aRow = tid >> 1;           // 0..127
    const int aCol = (tid & 1) * 4;      // 0 or 4
    const int bRow = tid >> 5;           // 0..7
    const int bCol = (tid & 31) * 4;     // 0..124
    const bool aInM = (row0 + aRow) < M;
    const float* Aptr = A + (size_t)(row0 + aRow) * K + aCol;

    for (int k0 = 0; k0 < K; k0 += 8) {
        float4 av = make_float4(0.f, 0.f, 0.f, 0.f);
        if (aInM) av = *reinterpret_cast<const float4*>(Aptr + k0);
        As[aCol + 0][aRow] = av.x;
        As[aCol + 1][aRow] = av.y;
        As[aCol + 2][aRow] = av.z;
        As[aCol + 3][aRow] = av.w;

        *reinterpret_cast<float4*>(&Bs[bRow][bCol]) =
            *reinterpret_cast<const float4*>(&B[(size_t)(k0 + bRow) * N + col0 + bCol]);
        __syncthreads();

        #pragma unroll
        for (int kk = 0; kk < 8; kk++) {
            float4 a0 = *reinterpret_cast<const float4*>(&As[kk][ty * 8]);
            float4 a1 = *reinterpret_cast<const float4*>(&As[kk][ty * 8 + 4]);
            float4 b0 = *reinterpret_cast<const float4*>(&Bs[kk][tx * 8]);
            float4 b1 = *reinterpret_cast<const float4*>(&Bs[kk][tx * 8 + 4]);
            float ar[8] = {a0.x, a0.y, a0.z, a0.w, a1.x, a1.y, a1.z, a1.w};
            float br[8] = {b0.x, b0.y, b0.z, b0.w, b1.x, b1.y, b1.z, b1.w};
            #pragma unroll
            for (int i = 0; i < 8; i++)
                #pragma unroll
                for (int j = 0; j < 8; j++)
                    acc[i][j] = fmaf(ar[i], br[j], acc[i][j]);
        }
        __syncthreads();
    }

    #pragma unroll
    for (int i = 0; i < 8; i++) {
        int r = row0 + ty * 8 + i;
        if (r >= M) continue;
        float* crow = C + (size_t)r * N + col0 + tx * 8;
        #pragma unroll
        for (int j = 0; j < 8; j += 4) {
            float4 v = make_float4(acc[i][j], acc[i][j + 1], acc[i][j + 2], acc[i][j + 3]);
            if (bias) {
                const float* bp = bias + col0 + tx * 8 + j;
                v.x += bp[0]; v.y += bp[1]; v.z += bp[2]; v.w += bp[3];
            }
            *reinterpret_cast<float4*>(crow + j) = v;
        }
    }
}

// ---------------------------------------------------------------------------
// Windowed attention: one block per (b, h, window). Thread = one query row.
// K/V streamed through smem in 64-key tiles; online softmax; q & acc in regs.
// ---------------------------------------------------------------------------
__global__ __launch_bounds__(256) void win_attn_kernel(
    const float* __restrict__ qkv, float* __restrict__ attn)
{
    __shared__ float Ks[64][DHEAD];
    __shared__ float Vs[64][DHEAD];

    const int w  = blockIdx.x;            // 0..1535
    const int fi = w % NF;
    const int bh = w / NF;
    const int h  = bh % NHEAD;
    const int b  = bh / NHEAD;
    const int tid = threadIdx.x;

    const size_t base = (size_t)b * NTOK * QKVCOLS;
    const int qcol = h * DHEAD;
    const int kcol = DMODEL + h * DHEAD;
    const int vcol = 2 * DMODEL + h * DHEAD;

    const int qi   = tid;                 // query index, valid < 196
    const int qtok = 1 + fi * NWIN + qi;

    float qreg[DHEAD];
    if (qi < NWIN) {
        const float* qp = qkv + base + (size_t)qtok * QKVCOLS + qcol;
        #pragma unroll
        for (int d = 0; d < DHEAD; d += 4) {
            float4 v = *reinterpret_cast<const float4*>(qp + d);
            qreg[d]     = v.x * 0.125f;
            qreg[d + 1] = v.y * 0.125f;
            qreg[d + 2] = v.z * 0.125f;
            qreg[d + 3] = v.w * 0.125f;
        }
    }

    float m = -1e30f, l = 0.f;
    float acc[DHEAD];
    #pragma unroll
    for (int d = 0; d < DHEAD; d++) acc[d] = 0.f;

    for (int j0 = 0; j0 < NKEY; j0 += 64) {
        const int tile = min(64, NKEY - j0);
        // cooperative load of K/V tile (16 float4 per row)
        for (int idx = tid; idx < tile * 16; idx += 256) {
            int jr = idx >> 4;
            int d4 = (idx & 15) * 4;
            int j  = j0 + jr;
            int tok = (j == 0) ? 0 : (1 + fi * NWIN + (j - 1));
            const float* rp = qkv + base + (size_t)tok * QKVCOLS;
            *reinterpret_cast<float4*>(&Ks[jr][d4]) =
                *reinterpret_cast<const float4*>(rp + kcol + d4);
            *reinterpret_cast<float4*>(&Vs[jr][d4]) =
                *reinterpret_cast<const float4*>(rp + vcol + d4);
        }
        __syncthreads();

        if (qi < NWIN) {
            for (int jr = 0; jr < tile; jr++) {
                float s = 0.f;
                #pragma unroll
                for (int d = 0; d < DHEAD; d++)
                    s = fmaf(qreg[d], Ks[jr][d], s);
                if (s > m) {                     // rare rescale
                    float corr = __expf(m - s);
                    l *= corr;
                    #pragma unroll
                    for (int d = 0; d < DHEAD; d++) acc[d] *= corr;
                    m = s;
                }
                float p = __expf(s - m);
                l += p;
                #pragma unroll
                for (int d = 0; d < DHEAD; d++)
                    acc[d] = fmaf(p, Vs[jr][d], acc[d]);
            }
        }
        __syncthreads();
    }

    if (qi < NWIN) {
        float inv = 1.f / l;
        float* op = attn + ((size_t)b * NTOK + qtok) * DMODEL + h * DHEAD;
        #pragma unroll
        for (int d = 0; d < DHEAD; d += 4) {
            float4 v = make_float4(acc[d] * inv, acc[d + 1] * inv,
                                   acc[d + 2] * inv, acc[d + 3] * inv);
            *reinterpret_cast<float4*>(op + d) = v;
        }
    }
}

// ---------------------------------------------------------------------------
// cls-token attention: one block per (b, h). Two-pass softmax over 1569 keys.
// ---------------------------------------------------------------------------
__global__ __launch_bounds__(256) void cls_attn_kernel(
    const float* __restrict__ qkv, float* __restrict__ attn)
{
    __shared__ float sims[NTOK];
    __shared__ float qs[DHEAD];
    __shared__ float red[256];

    const int bh = blockIdx.x;
    const int h  = bh % NHEAD;
    const int b  = bh / NHEAD;
    const int tid = threadIdx.x;

    const size_t base = (size_t)b * NTOK * QKVCOLS;
    const int qcol = h * DHEAD;
    const int kcol = DMODEL + h * DHEAD;
    const int vcol = 2 * DMODEL + h * DHEAD;

    if (tid < DHEAD) qs[tid] = qkv[base + qcol + tid] * 0.125f;
    __syncthreads();

    for (int j = tid; j < NTOK; j += 256) {
        const float* kp = qkv + base + (size_t)j * QKVCOLS + kcol;
        float s = 0.f;
        #pragma unroll
        for (int d = 0; d < DHEAD; d++) s = fmaf(qs[d], kp[d], s);
        sims[j] = s;
    }
    __syncthreads();

    // max
    float m = -1e30f;
    for (int j = tid; j < NTOK; j += 256) m = fmaxf(m, sims[j]);
    red[tid] = m; __syncthreads();
    for (int s2 = 128; s2 > 0; s2 >>= 1) {
        if (tid < s2) red[tid] = fmaxf(red[tid], red[tid + s2]);
        __syncthreads();
    }
    m = red[0]; __syncthreads();

    // exp + sum
    float lsum = 0.f;
    for (int j = tid; j < NTOK; j += 256) {
        float p = __expf(sims[j] - m);
        sims[j] = p;
        lsum += p;
    }
    red[tid] = lsum; __syncthreads();
    for (int s2 = 128; s2 > 0; s2 >>= 1) {
        if (tid < s2) red[tid] += red[tid + s2];
        __syncthreads();
    }
    float inv = 1.f / red[0];
    __syncthreads();

    // PV: tid = jg*64 + d
    const int d  = tid & 63;
    const int jg = tid >> 6;   // 0..3
    float o = 0.f;
    for (int j = jg; j < NTOK; j += 4)
        o = fmaf(sims[j], qkv[base + (size_t)j * QKVCOLS + vcol + d], o);
    red[tid] = o; __syncthreads();
    if (jg == 0) {
        o = red[d] + red[64 + d] + red[128 + d] + red[192 + d];
        attn[(size_t)b * NTOK * DMODEL + h * DHEAD + d] = o * inv;
    }
}

// ---------------------------------------------------------------------------
extern "C" void kernel_launch(void* const* d_in, const int* in_sizes, int n_in,
                              void* d_out, int out_size)
{
    const float* x      = (const float*)d_in[0];
    const float* w_qkv  = (const float*)d_in[1];
    const float* w_proj = (const float*)d_in[2];
    const float* b_proj = (const float*)d_in[3];
    float* out = (float*)d_out;

    float* qkv  = nullptr;
    float* attn = nullptr;
    cudaGetSymbolAddress((void**)&qkv,  g_qkv);
    cudaGetSymbolAddress((void**)&attn, g_attn);

    // 1) qkv = x @ w_qkv   [25104 x 2304]
    {
        dim3 grid(QKVCOLS / 128, (MROWS + 127) / 128);
        sgemm_kernel<<<grid, 256>>>(x, w_qkv, qkv, nullptr, MROWS, QKVCOLS, DMODEL);
    }
    // 2) windowed attention
    win_attn_kernel<<<BATCH * NHEAD * NF, 256>>>(qkv, attn);
    // 3) cls attention
    cls_attn_kernel<<<BATCH * NHEAD, 256>>>(qkv, attn);
    // 4) out = attn @ w_proj + b_proj   [25104 x 768]
    {
        dim3 grid(DMODEL / 128, (MROWS + 127) / 128);
        sgemm_kernel<<<grid, 256>>>(attn, w_proj, out, b_proj, MROWS, DMODEL, DMODEL);
    }
}

// round 3
// speedup vs baseline: 1.7676x; 1.7676x over previous
#include <cuda_runtime.h>
#include <cuda_bf16.h>
#include <cstdint>

// Problem constants (fixed by setup_inputs)
#define BATCH   16
#define NTOK    1569          // 1 + 8*196
#define DMODEL  768
#define NHEAD   12
#define DHEAD   64
#define NF      8
#define NWIN    196
#define NKEY    197
#define MROWS   (BATCH * NTOK)      // 25104
#define QKVCOLS (3 * DMODEL)        // 2304

// Scratch (allocation-free rule: __device__ globals)
__device__ float g_qkv [ (size_t)MROWS * QKVCOLS ];
__device__ float g_attn[ (size_t)MROWS * DMODEL  ];

// ===========================================================================
// TF32 mma.sync GEMM:  C[M,N] = A[M,K=768] @ B[768,N] (+bias)
// CTA 128x128, BK=16, double-buffered smem, 8 warps x (64x32 warp tile).
// ===========================================================================
#define GK   768
#define BK   16
#define NC   (GK / BK)        // 48
#define LDA  136              // 128 + 8 pad -> conflict-free fragment loads

__device__ __forceinline__ uint32_t f2tf32(float x) {
    uint32_t r;
    asm("cvt.rna.tf32.f32 %0, %1;" : "=r"(r) : "f"(x));
    return r;
}

__device__ __forceinline__ void mma_tf32(
    float& c0, float& c1, float& c2, float& c3,
    uint32_t a0, uint32_t a1, uint32_t a2, uint32_t a3,
    uint32_t b0, uint32_t b1)
{
    asm volatile(
        "mma.sync.aligned.m16n8k8.row.col.f32.tf32.tf32.f32 "
        "{%0,%1,%2,%3}, {%4,%5,%6,%7}, {%8,%9}, {%0,%1,%2,%3};"
        : "+f"(c0), "+f"(c1), "+f"(c2), "+f"(c3)
        : "r"(a0), "r"(a1), "r"(a2), "r"(a3), "r"(b0), "r"(b1));
}

__global__ __launch_bounds__(256) void mm_tf32_kernel(
    const float* __restrict__ A, const float* __restrict__ B,
    float* __restrict__ C, const float* __restrict__ bias, int M, int N)
{
    __shared__ uint32_t As[2][BK][LDA];   // [k][m] transposed
    __shared__ uint32_t Bs[2][BK][LDA];   // [k][n]

    const int tid  = threadIdx.x;
    const int wid  = tid >> 5;
    const int lane = tid & 31;
    const int lr   = lane >> 2;    // 0..7
    const int lc   = lane & 3;     // 0..3
    const int wr   = (wid & 1) * 64;
    const int wc   = (wid >> 1) * 32;
    const int row0 = blockIdx.y * 128;
    const int col0 = blockIdx.x * 128;

    // global-load mapping
    const int ar  = tid >> 1;            // A row 0..127
    const int ak  = (tid & 1) * 8;       // A k-offset 0 or 8
    const int bk  = tid >> 4;            // B k-row 0..15
    const int bn  = (tid & 15) * 8;      // B n-offset 0..120
    const bool aOk = (row0 + ar) < M;
    const float* Ap = A + (size_t)(row0 + ar) * GK + ak;
    const float* Bp = B + (size_t)bk * N + col0 + bn;

    float acc[4][4][4];
    #pragma unroll
    for (int i = 0; i < 4; i++)
        #pragma unroll
        for (int j = 0; j < 4; j++)
            #pragma unroll
            for (int q = 0; q < 4; q++) acc[i][j][q] = 0.f;

    float4 av0, av1, bv0, bv1;

    auto ldg_chunk = [&](int c) {
        const int k0 = c * BK;
        av0 = make_float4(0.f, 0.f, 0.f, 0.f);
        av1 = av0;
        if (aOk) {
            av0 = *reinterpret_cast<const float4*>(Ap + k0);
            av1 = *reinterpret_cast<const float4*>(Ap + k0 + 4);
        }
        bv0 = *reinterpret_cast<const float4*>(Bp + (size_t)k0 * N);
        bv1 = *reinterpret_cast<const float4*>(Bp + (size_t)k0 * N + 4);
    };
    auto sts_chunk = [&](int buf) {
        As[buf][ak + 0][ar] = f2tf32(av0.x);
        As[buf][ak + 1][ar] = f2tf32(av0.y);
        As[buf][ak + 2][ar] = f2tf32(av0.z);
        As[buf][ak + 3][ar] = f2tf32(av0.w);
        As[buf][ak + 4][ar] = f2tf32(av1.x);
        As[buf][ak + 5][ar] = f2tf32(av1.y);
        As[buf][ak + 6][ar] = f2tf32(av1.z);
        As[buf][ak + 7][ar] = f2tf32(av1.w);
        Bs[buf][bk][bn + 0] = f2tf32(bv0.x);
        Bs[buf][bk][bn + 1] = f2tf32(bv0.y);
        Bs[buf][bk][bn + 2] = f2tf32(bv0.z);
        Bs[buf][bk][bn + 3] = f2tf32(bv0.w);
        Bs[buf][bk][bn + 4] = f2tf32(bv1.x);
        Bs[buf][bk][bn + 5] = f2tf32(bv1.y);
        Bs[buf][bk][bn + 6] = f2tf32(bv1.z);
        Bs[buf][bk][bn + 7] = f2tf32(bv1.w);
    };

    ldg_chunk(0);
    sts_chunk(0);
    __syncthreads();

    for (int c = 0; c < NC; c++) {
        const int buf = c & 1;
        if (c + 1 < NC) ldg_chunk(c + 1);

        #pragma unroll
        for (int ks = 0; ks < 2; ks++) {
            const int kb = ks * 8;
            uint32_t af[4][4], bf[4][2];
            #pragma unroll
            for (int i = 0; i < 4; i++) {
                const int r = wr + i * 16 + lr;
                af[i][0] = As[buf][kb + lc][r];
                af[i][1] = As[buf][kb + lc][r + 8];
                af[i][2] = As[buf][kb + lc + 4][r];
                af[i][3] = As[buf][kb + lc + 4][r + 8];
            }
            #pragma unroll
            for (int j = 0; j < 4; j++) {
                const int n = wc + j * 8 + lr;
                bf[j][0] = Bs[buf][kb + lc][n];
                bf[j][1] = Bs[buf][kb + lc + 4][n];
            }
            #pragma unroll
            for (int i = 0; i < 4; i++)
                #pragma unroll
                for (int j = 0; j < 4; j++)
                    mma_tf32(acc[i][j][0], acc[i][j][1], acc[i][j][2], acc[i][j][3],
                             af[i][0], af[i][1], af[i][2], af[i][3],
                             bf[j][0], bf[j][1]);
        }

        __syncthreads();
        if (c + 1 < NC) {
            sts_chunk((c + 1) & 1);
            __syncthreads();
        }
    }

    // Epilogue
    #pragma unroll
    for (int i = 0; i < 4; i++) {
        const int r = row0 + wr + i * 16 + lr;
        #pragma unroll
        for (int j = 0; j < 4; j++) {
            const int n = col0 + wc + j * 8 + lc * 2;
            float b0 = 0.f, b1 = 0.f;
            if (bias) { b0 = bias[n]; b1 = bias[n + 1]; }
            if (r < M) {
                float2 v = make_float2(acc[i][j][0] + b0, acc[i][j][1] + b1);
                *reinterpret_cast<float2*>(&C[(size_t)r * N + n]) = v;
            }
            if (r + 8 < M) {
                float2 v = make_float2(acc[i][j][2] + b0, acc[i][j][3] + b1);
                *reinterpret_cast<float2*>(&C[(size_t)(r + 8) * N + n]) = v;
            }
        }
    }
}

// ---------------------------------------------------------------------------
// Windowed attention: one block per (b, h, window). Thread = one query row.
// ---------------------------------------------------------------------------
__global__ __launch_bounds__(256) void win_attn_kernel(
    const float* __restrict__ qkv, float* __restrict__ attn)
{
    __shared__ float Ks[64][DHEAD];
    __shared__ float Vs[64][DHEAD];

    const int w  = blockIdx.x;
    const int fi = w % NF;
    const int bh = w / NF;
    const int h  = bh % NHEAD;
    const int b  = bh / NHEAD;
    const int tid = threadIdx.x;

    const size_t base = (size_t)b * NTOK * QKVCOLS;
    const int qcol = h * DHEAD;
    const int kcol = DMODEL + h * DHEAD;
    const int vcol = 2 * DMODEL + h * DHEAD;

    const int qi   = tid;
    const int qtok = 1 + fi * NWIN + qi;

    float qreg[DHEAD];
    if (qi < NWIN) {
        const float* qp = qkv + base + (size_t)qtok * QKVCOLS + qcol;
        #pragma unroll
        for (int d = 0; d < DHEAD; d += 4) {
            float4 v = *reinterpret_cast<const float4*>(qp + d);
            qreg[d]     = v.x * 0.125f;
            qreg[d + 1] = v.y * 0.125f;
            qreg[d + 2] = v.z * 0.125f;
            qreg[d + 3] = v.w * 0.125f;
        }
    }

    float m = -1e30f, l = 0.f;
    float acc[DHEAD];
    #pragma unroll
    for (int d = 0; d < DHEAD; d++) acc[d] = 0.f;

    for (int j0 = 0; j0 < NKEY; j0 += 64) {
        const int tile = min(64, NKEY - j0);
        for (int idx = tid; idx < tile * 16; idx += 256) {
            int jr = idx >> 4;
            int d4 = (idx & 15) * 4;
            int j  = j0 + jr;
            int tok = (j == 0) ? 0 : (1 + fi * NWIN + (j - 1));
            const float* rp = qkv + base + (size_t)tok * QKVCOLS;
            *reinterpret_cast<float4*>(&Ks[jr][d4]) =
                *reinterpret_cast<const float4*>(rp + kcol + d4);
            *reinterpret_cast<float4*>(&Vs[jr][d4]) =
                *reinterpret_cast<const float4*>(rp + vcol + d4);
        }
        __syncthreads();

        if (qi < NWIN) {
            for (int jr = 0; jr < tile; jr++) {
                float s = 0.f;
                #pragma unroll
                for (int d = 0; d < DHEAD; d++)
                    s = fmaf(qreg[d], Ks[jr][d], s);
                if (s > m) {
                    float corr = __expf(m - s);
                    l *= corr;
                    #pragma unroll
                    for (int d = 0; d < DHEAD; d++) acc[d] *= corr;
                    m = s;
                }
                float p = __expf(s - m);
                l += p;
                #pragma unroll
                for (int d = 0; d < DHEAD; d++)
                    acc[d] = fmaf(p, Vs[jr][d], acc[d]);
            }
        }
        __syncthreads();
    }

    if (qi < NWIN) {
        float inv = 1.f / l;
        float* op = attn + ((size_t)b * NTOK + qtok) * DMODEL + h * DHEAD;
        #pragma unroll
        for (int d = 0; d < DHEAD; d += 4) {
            float4 v = make_float4(acc[d] * inv, acc[d + 1] * inv,
                                   acc[d + 2] * inv, acc[d + 3] * inv);
            *reinterpret_cast<float4*>(op + d) = v;
        }
    }
}

// ---------------------------------------------------------------------------
// cls-token attention: one block per (b, h).
// ---------------------------------------------------------------------------
__global__ __launch_bounds__(256) void cls_attn_kernel(
    const float* __restrict__ qkv, float* __restrict__ attn)
{
    __shared__ float sims[NTOK];
    __shared__ float qs[DHEAD];
    __shared__ float red[256];

    const int bh = blockIdx.x;
    const int h  = bh % NHEAD;
    const int b  = bh / NHEAD;
    const int tid = threadIdx.x;

    const size_t base = (size_t)b * NTOK * QKVCOLS;
    const int qcol = h * DHEAD;
    const int kcol = DMODEL + h * DHEAD;
    const int vcol = 2 * DMODEL + h * DHEAD;

    if (tid < DHEAD) qs[tid] = qkv[base + qcol + tid] * 0.125f;
    __syncthreads();

    for (int j = tid; j < NTOK; j += 256) {
        const float* kp = qkv + base + (size_t)j * QKVCOLS + kcol;
        float s = 0.f;
        #pragma unroll
        for (int d = 0; d < DHEAD; d++) s = fmaf(qs[d], kp[d], s);
        sims[j] = s;
    }
    __syncthreads();

    float m = -1e30f;
    for (int j = tid; j < NTOK; j += 256) m = fmaxf(m, sims[j]);
    red[tid] = m; __syncthreads();
    for (int s2 = 128; s2 > 0; s2 >>= 1) {
        if (tid < s2) red[tid] = fmaxf(red[tid], red[tid + s2]);
        __syncthreads();
    }
    m = red[0]; __syncthreads();

    float lsum = 0.f;
    for (int j = tid; j < NTOK; j += 256) {
        float p = __expf(sims[j] - m);
        sims[j] = p;
        lsum += p;
    }
    red[tid] = lsum; __syncthreads();
    for (int s2 = 128; s2 > 0; s2 >>= 1) {
        if (tid < s2) red[tid] += red[tid + s2];
        __syncthreads();
    }
    float inv = 1.f / red[0];
    __syncthreads();

    const int d  = tid & 63;
    const int jg = tid >> 6;
    float o = 0.f;
    for (int j = jg; j < NTOK; j += 4)
        o = fmaf(sims[j], qkv[base + (size_t)j * QKVCOLS + vcol + d], o);
    red[tid] = o; __syncthreads();
    if (jg == 0) {
        o = red[d] + red[64 + d] + red[128 + d] + red[192 + d];
        attn[(size_t)b * NTOK * DMODEL + h * DHEAD + d] = o * inv;
    }
}

// ---------------------------------------------------------------------------
extern "C" void kernel_launch(void* const* d_in, const int* in_sizes, int n_in,
                              void* d_out, int out_size)
{
    const float* x      = (const float*)d_in[0];
    const float* w_qkv  = (const float*)d_in[1];
    const float* w_proj = (const float*)d_in[2];
    const float* b_proj = (const float*)d_in[3];
    float* out = (float*)d_out;

    float* qkv  = nullptr;
    float* attn = nullptr;
    cudaGetSymbolAddress((void**)&qkv,  g_qkv);
    cudaGetSymbolAddress((void**)&attn, g_attn);

    // 1) qkv = x @ w_qkv   [25104 x 2304]
    {
        dim3 grid(QKVCOLS / 128, (MROWS + 127) / 128);
        mm_tf32_kernel<<<grid, 256>>>(x, w_qkv, qkv, nullptr, MROWS, QKVCOLS);
    }
    // 2) windowed attention
    win_attn_kernel<<<BATCH * NHEAD * NF, 256>>>(qkv, attn);
    // 3) cls attention
    cls_attn_kernel<<<BATCH * NHEAD, 256>>>(qkv, attn);
    // 4) out = attn @ w_proj + b_proj   [25104 x 768]
    {
        dim3 grid(DMODEL / 128, (MROWS + 127) / 128);
        mm_tf32_kernel<<<grid, 256>>>(attn, w_proj, out, b_proj, MROWS, DMODEL);
    }
}

// round 4
// speedup vs baseline: 2.3387x; 1.3231x over previous
#include <cuda_runtime.h>
#include <cuda_bf16.h>
#include <cstdint>

// Problem constants (fixed by setup_inputs)
#define BATCH   16
#define NTOK    1569          // 1 + 8*196
#define DMODEL  768
#define NHEAD   12
#define DHEAD   64
#define NF      8
#define NWIN    196
#define NKEY    197
#define MROWS   (BATCH * NTOK)      // 25104
#define QKVCOLS (3 * DMODEL)        // 2304

// Scratch (allocation-free rule: __device__ globals)
__device__ float g_qkv [ (size_t)MROWS * QKVCOLS ];
__device__ float g_attn[ (size_t)MROWS * DMODEL  ];

__device__ __forceinline__ uint32_t f2tf32(float x) {
    uint32_t r;
    asm("cvt.rna.tf32.f32 %0, %1;" : "=r"(r) : "f"(x));
    return r;
}

__device__ __forceinline__ void mma_tf32(
    float& c0, float& c1, float& c2, float& c3,
    uint32_t a0, uint32_t a1, uint32_t a2, uint32_t a3,
    uint32_t b0, uint32_t b1)
{
    asm volatile(
        "mma.sync.aligned.m16n8k8.row.col.f32.tf32.tf32.f32 "
        "{%0,%1,%2,%3}, {%4,%5,%6,%7}, {%8,%9}, {%0,%1,%2,%3};"
        : "+f"(c0), "+f"(c1), "+f"(c2), "+f"(c3)
        : "r"(a0), "r"(a1), "r"(a2), "r"(a3), "r"(b0), "r"(b1));
}

// ===========================================================================
// TF32 mma.sync GEMM:  C[M,N] = A[M,K=768] @ B[768,N] (+bias)
// CTA 128x128, BK=16, double-buffered smem, 8 warps x (64x32 warp tile).
// ===========================================================================
#define GK   768
#define BK   16
#define NC   (GK / BK)        // 48
#define LDA  136

__global__ __launch_bounds__(256) void mm_tf32_kernel(
    const float* __restrict__ A, const float* __restrict__ B,
    float* __restrict__ C, const float* __restrict__ bias, int M, int N)
{
    __shared__ uint32_t As[2][BK][LDA];   // [k][m] transposed
    __shared__ uint32_t Bs[2][BK][LDA];   // [k][n]

    const int tid  = threadIdx.x;
    const int wid  = tid >> 5;
    const int lane = tid & 31;
    const int lr   = lane >> 2;
    const int lc   = lane & 3;
    const int wr   = (wid & 1) * 64;
    const int wc   = (wid >> 1) * 32;
    const int row0 = blockIdx.y * 128;
    const int col0 = blockIdx.x * 128;

    const int ar  = tid >> 1;
    const int ak  = (tid & 1) * 8;
    const int bk  = tid >> 4;
    const int bn  = (tid & 15) * 8;
    const bool aOk = (row0 + ar) < M;
    const float* Ap = A + (size_t)(row0 + ar) * GK + ak;
    const float* Bp = B + (size_t)bk * N + col0 + bn;

    float acc[4][4][4];
    #pragma unroll
    for (int i = 0; i < 4; i++)
        #pragma unroll
        for (int j = 0; j < 4; j++)
            #pragma unroll
            for (int q = 0; q < 4; q++) acc[i][j][q] = 0.f;

    float4 av0, av1, bv0, bv1;

    auto ldg_chunk = [&](int c) {
        const int k0 = c * BK;
        av0 = make_float4(0.f, 0.f, 0.f, 0.f);
        av1 = av0;
        if (aOk) {
            av0 = *reinterpret_cast<const float4*>(Ap + k0);
            av1 = *reinterpret_cast<const float4*>(Ap + k0 + 4);
        }
        bv0 = *reinterpret_cast<const float4*>(Bp + (size_t)k0 * N);
        bv1 = *reinterpret_cast<const float4*>(Bp + (size_t)k0 * N + 4);
    };
    auto sts_chunk = [&](int buf) {
        As[buf][ak + 0][ar] = f2tf32(av0.x);
        As[buf][ak + 1][ar] = f2tf32(av0.y);
        As[buf][ak + 2][ar] = f2tf32(av0.z);
        As[buf][ak + 3][ar] = f2tf32(av0.w);
        As[buf][ak + 4][ar] = f2tf32(av1.x);
        As[buf][ak + 5][ar] = f2tf32(av1.y);
        As[buf][ak + 6][ar] = f2tf32(av1.z);
        As[buf][ak + 7][ar] = f2tf32(av1.w);
        Bs[buf][bk][bn + 0] = f2tf32(bv0.x);
        Bs[buf][bk][bn + 1] = f2tf32(bv0.y);
        Bs[buf][bk][bn + 2] = f2tf32(bv0.z);
        Bs[buf][bk][bn + 3] = f2tf32(bv0.w);
        Bs[buf][bk][bn + 4] = f2tf32(bv1.x);
        Bs[buf][bk][bn + 5] = f2tf32(bv1.y);
        Bs[buf][bk][bn + 6] = f2tf32(bv1.z);
        Bs[buf][bk][bn + 7] = f2tf32(bv1.w);
    };

    ldg_chunk(0);
    sts_chunk(0);
    __syncthreads();

    for (int c = 0; c < NC; c++) {
        const int buf = c & 1;
        if (c + 1 < NC) ldg_chunk(c + 1);

        #pragma unroll
        for (int ks = 0; ks < 2; ks++) {
            const int kb = ks * 8;
            uint32_t af[4][4], bf[4][2];
            #pragma unroll
            for (int i = 0; i < 4; i++) {
                const int r = wr + i * 16 + lr;
                af[i][0] = As[buf][kb + lc][r];
                af[i][1] = As[buf][kb + lc][r + 8];
                af[i][2] = As[buf][kb + lc + 4][r];
                af[i][3] = As[buf][kb + lc + 4][r + 8];
            }
            #pragma unroll
            for (int j = 0; j < 4; j++) {
                const int n = wc + j * 8 + lr;
                bf[j][0] = Bs[buf][kb + lc][n];
                bf[j][1] = Bs[buf][kb + lc + 4][n];
            }
            #pragma unroll
            for (int i = 0; i < 4; i++)
                #pragma unroll
                for (int j = 0; j < 4; j++)
                    mma_tf32(acc[i][j][0], acc[i][j][1], acc[i][j][2], acc[i][j][3],
                             af[i][0], af[i][1], af[i][2], af[i][3],
                             bf[j][0], bf[j][1]);
        }

        __syncthreads();
        if (c + 1 < NC) {
            sts_chunk((c + 1) & 1);
            __syncthreads();
        }
    }

    #pragma unroll
    for (int i = 0; i < 4; i++) {
        const int r = row0 + wr + i * 16 + lr;
        #pragma unroll
        for (int j = 0; j < 4; j++) {
            const int n = col0 + wc + j * 8 + lc * 2;
            float b0 = 0.f, b1 = 0.f;
            if (bias) { b0 = bias[n]; b1 = bias[n + 1]; }
            if (r < M) {
                float2 v = make_float2(acc[i][j][0] + b0, acc[i][j][1] + b1);
                *reinterpret_cast<float2*>(&C[(size_t)r * N + n]) = v;
            }
            if (r + 8 < M) {
                float2 v = make_float2(acc[i][j][2] + b0, acc[i][j][3] + b1);
                *reinterpret_cast<float2*>(&C[(size_t)(r + 8) * N + n]) = v;
            }
        }
    }
}

// ===========================================================================
// Tensor-core windowed attention. One block per (b,h,window), 512 threads.
// S chunk-materialized in smem; Q frags in regs; O frags in regs with
// online-softmax rescale. All MMAs tf32.
// ===========================================================================
#define MPAD   208            // 13 m-tiles of 16 (>=196)
#define SSLD   132            // Ss stride (words): %32==4 -> conflict-free frags
#define KCLD   68             // Kc stride: %32==4
#define VCLD   72             // Vc stride: %32==8
#define SS_W   (MPAD * SSLD)              // 27456
#define KC_W   (128 * KCLD)               // 8704
#define VC_W   (128 * VCLD)               // 9216
#define WA_SMEM ((SS_W + KC_W + VC_W + 3 * MPAD) * 4)   // 184000 B

__global__ __launch_bounds__(512, 1) void win_attn_mma_kernel(
    const float* __restrict__ qkv, float* __restrict__ attn)
{
    extern __shared__ float sm[];
    float*    Ss  = sm;                       // [208][132] fp32 S, then tf32 P
    uint32_t* Su  = reinterpret_cast<uint32_t*>(sm);
    uint32_t* Kc  = reinterpret_cast<uint32_t*>(sm + SS_W);      // [128][68]
    uint32_t* Vc  = Kc + KC_W;                                   // [128][72]
    float*    msm = reinterpret_cast<float*>(Vc + VC_W);
    float*    lsm = msm + MPAD;
    float*    fs  = lsm + MPAD;

    const int w  = blockIdx.x;
    const int fi = w % NF;
    const int bh = w / NF;
    const int h  = bh % NHEAD;
    const int b  = bh / NHEAD;
    const int tid  = threadIdx.x;
    const int wid  = tid >> 5;     // 0..15, warps 0..12 do MMA
    const int lane = tid & 31;
    const int lr   = lane >> 2;
    const int lc   = lane & 3;

    const size_t base = (size_t)b * NTOK * QKVCOLS;
    const int qcol = h * DHEAD;
    const int kcol = DMODEL + h * DHEAD;
    const int vcol = 2 * DMODEL + h * DHEAD;

    for (int r = tid; r < MPAD; r += 512) { msm[r] = -1e30f; lsm[r] = 0.f; }

    // Q fragments (warp `wid` owns m-tile `wid`: rows 16*wid + lr, +8)
    uint32_t qf[8][4];
    const int r0 = wid * 16 + lr;
    const int r1 = r0 + 8;
    {
        const bool v0 = (wid < 13) && (r0 < NWIN);
        const bool v1 = (wid < 13) && (r1 < NWIN);
        const float* q0 = qkv + base + (size_t)(1 + fi * NWIN + r0) * QKVCOLS + qcol;
        const float* q1 = qkv + base + (size_t)(1 + fi * NWIN + r1) * QKVCOLS + qcol;
        #pragma unroll
        for (int ks = 0; ks < 8; ks++) {
            const int d0 = ks * 8 + lc;
            qf[ks][0] = v0 ? f2tf32(q0[d0]     * 0.125f) : 0u;
            qf[ks][1] = v1 ? f2tf32(q1[d0]     * 0.125f) : 0u;
            qf[ks][2] = v0 ? f2tf32(q0[d0 + 4] * 0.125f) : 0u;
            qf[ks][3] = v1 ? f2tf32(q1[d0 + 4] * 0.125f) : 0u;
        }
    }

    float O[8][4];
    #pragma unroll
    for (int dt = 0; dt < 8; dt++)
        #pragma unroll
        for (int q = 0; q < 4; q++) O[dt][q] = 0.f;

    for (int c = 0; c < 2; c++) {
        const int len    = (c == 0) ? 128 : (NKEY - 128);   // 128, 69
        const int ntiles = (len + 7) >> 3;                   // 16, 9
        const int pl     = ntiles * 8;                       // 128, 72

        // ---- load K/V chunk (tf32) ----
        for (int idx = tid; idx < pl * 16; idx += 512) {
            const int kr = idx >> 4;
            const int d4 = (idx & 15) * 4;
            const int gk = c * 128 + kr;
            float4 kv = make_float4(0.f, 0.f, 0.f, 0.f), vv = kv;
            if (gk < NKEY) {
                const int tok = (gk == 0) ? 0 : (1 + fi * NWIN + (gk - 1));
                const float* rp = qkv + base + (size_t)tok * QKVCOLS;
                kv = *reinterpret_cast<const float4*>(rp + kcol + d4);
                vv = *reinterpret_cast<const float4*>(rp + vcol + d4);
            }
            uint32_t* kp = Kc + kr * KCLD + d4;
            kp[0] = f2tf32(kv.x); kp[1] = f2tf32(kv.y);
            kp[2] = f2tf32(kv.z); kp[3] = f2tf32(kv.w);
            uint32_t* vp = Vc + kr * VCLD + d4;
            vp[0] = f2tf32(vv.x); vp[1] = f2tf32(vv.y);
            vp[2] = f2tf32(vv.z); vp[3] = f2tf32(vv.w);
        }
        __syncthreads();

        // ---- S = Q @ K^T ----
        if (wid < 13) {
            for (int nt = 0; nt < ntiles; nt++) {
                float a0 = 0.f, a1 = 0.f, a2 = 0.f, a3 = 0.f;
                const uint32_t* kb = Kc + (nt * 8 + lr) * KCLD + lc;
                #pragma unroll
                for (int ks = 0; ks < 8; ks++) {
                    uint32_t b0 = kb[ks * 8];
                    uint32_t b1 = kb[ks * 8 + 4];
                    mma_tf32(a0, a1, a2, a3,
                             qf[ks][0], qf[ks][1], qf[ks][2], qf[ks][3], b0, b1);
                }
                *reinterpret_cast<float2*>(&Ss[r0 * SSLD + nt * 8 + 2 * lc]) =
                    make_float2(a0, a1);
                *reinterpret_cast<float2*>(&Ss[r1 * SSLD + nt * 8 + 2 * lc]) =
                    make_float2(a2, a3);
            }
        }
        __syncthreads();

        // ---- softmax rows (thread r handles row r) ----
        if (tid < MPAD) {
            const int r = tid;
            float* srow = Ss + r * SSLD;
            const float mold = msm[r];
            float mc = mold;
            for (int j = 0; j < len; j++) mc = fmaxf(mc, srow[j]);
            const float f = __expf(mold - mc);
            float ls = 0.f;
            uint32_t* prow = Su + r * SSLD;
            for (int j = 0; j < pl; j++) {
                float p = (j < len) ? __expf(srow[j] - mc) : 0.f;
                ls += p;
                prow[j] = f2tf32(p);
            }
            msm[r] = mc;
            lsm[r] = lsm[r] * f + ls;
            fs[r]  = f;
        }
        __syncthreads();

        // ---- O = O*f + P @ V ----
        if (wid < 13) {
            const float f0 = fs[r0];
            const float f1 = fs[r1];
            #pragma unroll
            for (int dt = 0; dt < 8; dt++) {
                O[dt][0] *= f0; O[dt][1] *= f0;
                O[dt][2] *= f1; O[dt][3] *= f1;
            }
            for (int kt = 0; kt < ntiles; kt++) {
                const uint32_t pa0 = Su[r0 * SSLD + kt * 8 + lc];
                const uint32_t pa1 = Su[r1 * SSLD + kt * 8 + lc];
                const uint32_t pa2 = Su[r0 * SSLD + kt * 8 + lc + 4];
                const uint32_t pa3 = Su[r1 * SSLD + kt * 8 + lc + 4];
                const uint32_t* v0 = Vc + (kt * 8 + lc) * VCLD + lr;
                const uint32_t* v1 = Vc + (kt * 8 + lc + 4) * VCLD + lr;
                #pragma unroll
                for (int dt = 0; dt < 8; dt++) {
                    mma_tf32(O[dt][0], O[dt][1], O[dt][2], O[dt][3],
                             pa0, pa1, pa2, pa3, v0[dt * 8], v1[dt * 8]);
                }
            }
        }
        __syncthreads();
    }

    // ---- write output ----
    if (wid < 13) {
        const bool v0 = r0 < NWIN;
        const bool v1 = r1 < NWIN;
        const float inv0 = v0 ? (1.f / lsm[r0]) : 0.f;
        const float inv1 = v1 ? (1.f / lsm[r1]) : 0.f;
        float* o0 = attn + ((size_t)b * NTOK + 1 + fi * NWIN + r0) * DMODEL + h * DHEAD;
        float* o1 = attn + ((size_t)b * NTOK + 1 + fi * NWIN + r1) * DMODEL + h * DHEAD;
        #pragma unroll
        for (int dt = 0; dt < 8; dt++) {
            const int d = dt * 8 + 2 * lc;
            if (v0) *reinterpret_cast<float2*>(o0 + d) =
                make_float2(O[dt][0] * inv0, O[dt][1] * inv0);
            if (v1) *reinterpret_cast<float2*>(o1 + d) =
                make_float2(O[dt][2] * inv1, O[dt][3] * inv1);
        }
    }
}

// ---------------------------------------------------------------------------
// cls-token attention: one block per (b, h). Scalar fp32 (tiny).
// ---------------------------------------------------------------------------
__global__ __launch_bounds__(256) void cls_attn_kernel(
    const float* __restrict__ qkv, float* __restrict__ attn)
{
    __shared__ float sims[NTOK];
    __shared__ float qs[DHEAD];
    __shared__ float red[256];

    const int bh = blockIdx.x;
    const int h  = bh % NHEAD;
    const int b  = bh / NHEAD;
    const int tid = threadIdx.x;

    const size_t base = (size_t)b * NTOK * QKVCOLS;
    const int qcol = h * DHEAD;
    const int kcol = DMODEL + h * DHEAD;
    const int vcol = 2 * DMODEL + h * DHEAD;

    if (tid < DHEAD) qs[tid] = qkv[base + qcol + tid] * 0.125f;
    __syncthreads();

    for (int j = tid; j < NTOK; j += 256) {
        const float* kp = qkv + base + (size_t)j * QKVCOLS + kcol;
        float s = 0.f;
        #pragma unroll
        for (int d = 0; d < DHEAD; d++) s = fmaf(qs[d], kp[d], s);
        sims[j] = s;
    }
    __syncthreads();

    float m = -1e30f;
    for (int j = tid; j < NTOK; j += 256) m = fmaxf(m, sims[j]);
    red[tid] = m; __syncthreads();
    for (int s2 = 128; s2 > 0; s2 >>= 1) {
        if (tid < s2) red[tid] = fmaxf(red[tid], red[tid + s2]);
        __syncthreads();
    }
    m = red[0]; __syncthreads();

    float lsum = 0.f;
    for (int j = tid; j < NTOK; j += 256) {
        float p = __expf(sims[j] - m);
        sims[j] = p;
        lsum += p;
    }
    red[tid] = lsum; __syncthreads();
    for (int s2 = 128; s2 > 0; s2 >>= 1) {
        if (tid < s2) red[tid] += red[tid + s2];
        __syncthreads();
    }
    float inv = 1.f / red[0];
    __syncthreads();

    const int d  = tid & 63;
    const int jg = tid >> 6;
    float o = 0.f;
    for (int j = jg; j < NTOK; j += 4)
        o = fmaf(sims[j], qkv[base + (size_t)j * QKVCOLS + vcol + d], o);
    red[tid] = o; __syncthreads();
    if (jg == 0) {
        o = red[d] + red[64 + d] + red[128 + d] + red[192 + d];
        attn[(size_t)b * NTOK * DMODEL + h * DHEAD + d] = o * inv;
    }
}

// ---------------------------------------------------------------------------
extern "C" void kernel_launch(void* const* d_in, const int* in_sizes, int n_in,
                              void* d_out, int out_size)
{
    const float* x      = (const float*)d_in[0];
    const float* w_qkv  = (const float*)d_in[1];
    const float* w_proj = (const float*)d_in[2];
    const float* b_proj = (const float*)d_in[3];
    float* out = (float*)d_out;

    float* qkv  = nullptr;
    float* attn = nullptr;
    cudaGetSymbolAddress((void**)&qkv,  g_qkv);
    cudaGetSymbolAddress((void**)&attn, g_attn);

    cudaFuncSetAttribute(win_attn_mma_kernel,
                         cudaFuncAttributeMaxDynamicSharedMemorySize, WA_SMEM);

    // 1) qkv = x @ w_qkv   [25104 x 2304]
    {
        dim3 grid(QKVCOLS / 128, (MROWS + 127) / 128);
        mm_tf32_kernel<<<grid, 256>>>(x, w_qkv, qkv, nullptr, MROWS, QKVCOLS);
    }
    // 2) windowed attention (tensor cores)
    win_attn_mma_kernel<<<BATCH * NHEAD * NF, 512, WA_SMEM>>>(qkv, attn);
    // 3) cls attention
    cls_attn_kernel<<<BATCH * NHEAD, 256>>>(qkv, attn);
    // 4) out = attn @ w_proj + b_proj   [25104 x 768]
    {
        dim3 grid(DMODEL / 128, (MROWS + 127) / 128);
        mm_tf32_kernel<<<grid, 256>>>(attn, w_proj, out, b_proj, MROWS, DMODEL);
    }
}

// round 5
// speedup vs baseline: 2.5122x; 1.0742x over previous
#include <cuda_runtime.h>
#include <cuda_bf16.h>
#include <cstdint>

// Problem constants (fixed by setup_inputs)
#define BATCH   16
#define NTOK    1569          // 1 + 8*196
#define DMODEL  768
#define NHEAD   12
#define DHEAD   64
#define NF      8
#define NWIN    196
#define NKEY    197
#define MROWS   (BATCH * NTOK)      // 25104
#define QKVCOLS (3 * DMODEL)        // 2304

// Scratch (allocation-free rule: __device__ globals)
__device__ float g_qkv [ (size_t)MROWS * QKVCOLS ];
__device__ float g_attn[ (size_t)MROWS * DMODEL  ];

__device__ __forceinline__ uint32_t f2tf32(float x) {
    uint32_t r;
    asm("cvt.rna.tf32.f32 %0, %1;" : "=r"(r) : "f"(x));
    return r;
}

__device__ __forceinline__ void mma_tf32(
    float& c0, float& c1, float& c2, float& c3,
    uint32_t a0, uint32_t a1, uint32_t a2, uint32_t a3,
    uint32_t b0, uint32_t b1)
{
    asm volatile(
        "mma.sync.aligned.m16n8k8.row.col.f32.tf32.tf32.f32 "
        "{%0,%1,%2,%3}, {%4,%5,%6,%7}, {%8,%9}, {%0,%1,%2,%3};"
        : "+f"(c0), "+f"(c1), "+f"(c2), "+f"(c3)
        : "r"(a0), "r"(a1), "r"(a2), "r"(a3), "r"(b0), "r"(b1));
}

// ===========================================================================
// TF32 mma.sync GEMM:  C[M,N] = A[M,K=768] @ B[768,N] (+bias)
// CTA 128x128, BK=16, double-buffered smem with K-PAIRED 64-bit layout:
//   Asp[kg][m][p]  = (tf32 A[m][kb+p], tf32 A[m][kb+p+4])  stride 4 uint2
//   Bsp[kg][n][p]  = (tf32 B[kb+p][n], tf32 B[kb+p+4][n])  stride 5 uint2 (pad)
// -> fragment loads are LDS.64 (half the instruction count of R4).
// ===========================================================================
#define GK   768
#define BK   16
#define NC   (GK / BK)        // 48
#define APB  (2 * 128 * 4)    // uint2 per A buffer (1024)
#define BPB  (2 * 128 * 5)    // uint2 per B buffer (1280)

__global__ __launch_bounds__(256, 2) void mm_tf32_kernel(
    const float* __restrict__ A, const float* __restrict__ B,
    float* __restrict__ C, const float* __restrict__ bias, int M, int N)
{
    __shared__ uint2 Asp[2][APB];
    __shared__ uint2 Bsp[2][BPB];

    const int tid  = threadIdx.x;
    const int wid  = tid >> 5;
    const int lane = tid & 31;
    const int lr   = lane >> 2;
    const int lc   = lane & 3;
    const int wr   = (wid & 1) * 64;
    const int wc   = (wid >> 1) * 32;
    const int row0 = blockIdx.y * 128;
    const int col0 = blockIdx.x * 128;

    // A global-load mapping: row ar, k-group kg (8 k's)
    const int ar   = tid >> 1;           // 0..127
    const int akg  = tid & 1;            // 0,1
    const bool aOk = (row0 + ar) < M;
    const float* Ap = A + (size_t)(row0 + ar) * GK + akg * 8;

    // B global-load mapping: k-group kgb, pair p, lane ln (4 n-cols of 32)
    const int kgb = tid >> 7;            // 0,1
    const int pb  = (tid >> 5) & 3;      // 0..3
    const int ln  = tid & 31;            // 0..31
    const float* Bp0 = B + (size_t)(kgb * 8 + pb) * N + col0 + ln;
    const float* Bp1 = Bp0 + 4 * (size_t)N;

    float acc[4][4][4];
    #pragma unroll
    for (int i = 0; i < 4; i++)
        #pragma unroll
        for (int j = 0; j < 4; j++)
            #pragma unroll
            for (int q = 0; q < 4; q++) acc[i][j][q] = 0.f;

    float4 av0, av1;
    float  bl[4], bh[4];

    auto ldg_chunk = [&](int c) {
        const int k0 = c * BK;
        av0 = make_float4(0.f, 0.f, 0.f, 0.f);
        av1 = av0;
        if (aOk) {
            av0 = *reinterpret_cast<const float4*>(Ap + k0);
            av1 = *reinterpret_cast<const float4*>(Ap + k0 + 4);
        }
        const size_t ko = (size_t)k0 * N;
        #pragma unroll
        for (int j = 0; j < 4; j++) {
            bl[j] = Bp0[ko + 32 * j];
            bh[j] = Bp1[ko + 32 * j];
        }
    };
    auto sts_chunk = [&](int buf) {
        // A pairs: p -> (av0[p], av1[p]); two STS.128
        uint2* ap = &Asp[buf][(akg * 128 + ar) * 4];
        uint4 w0 = make_uint4(f2tf32(av0.x), f2tf32(av1.x),
                              f2tf32(av0.y), f2tf32(av1.y));
        uint4 w1 = make_uint4(f2tf32(av0.z), f2tf32(av1.z),
                              f2tf32(av0.w), f2tf32(av1.w));
        *reinterpret_cast<uint4*>(ap)     = w0;   // p=0,1
        *reinterpret_cast<uint4*>(ap + 2) = w1;   // p=2,3
        // B pairs
        #pragma unroll
        for (int j = 0; j < 4; j++)
            Bsp[buf][(kgb * 128 + ln + 32 * j) * 5 + pb] =
                make_uint2(f2tf32(bl[j]), f2tf32(bh[j]));
    };

    ldg_chunk(0);
    sts_chunk(0);
    __syncthreads();

    for (int c = 0; c < NC; c++) {
        const int buf = c & 1;
        if (c + 1 < NC) ldg_chunk(c + 1);

        #pragma unroll
        for (int kg = 0; kg < 2; kg++) {
            uint2 pa[4][2];
            #pragma unroll
            for (int i = 0; i < 4; i++) {
                const int r = wr + i * 16 + lr;
                pa[i][0] = Asp[buf][(kg * 128 + r) * 4 + lc];
                pa[i][1] = Asp[buf][(kg * 128 + r + 8) * 4 + lc];
            }
            uint2 pbf[4];
            #pragma unroll
            for (int j = 0; j < 4; j++) {
                const int n = wc + j * 8 + lr;
                pbf[j] = Bsp[buf][(kg * 128 + n) * 5 + lc];
            }
            #pragma unroll
            for (int i = 0; i < 4; i++)
                #pragma unroll
                for (int j = 0; j < 4; j++)
                    mma_tf32(acc[i][j][0], acc[i][j][1], acc[i][j][2], acc[i][j][3],
                             pa[i][0].x, pa[i][1].x, pa[i][0].y, pa[i][1].y,
                             pbf[j].x, pbf[j].y);
        }

        __syncthreads();
        if (c + 1 < NC) {
            sts_chunk((c + 1) & 1);
            __syncthreads();
        }
    }

    #pragma unroll
    for (int i = 0; i < 4; i++) {
        const int r = row0 + wr + i * 16 + lr;
        #pragma unroll
        for (int j = 0; j < 4; j++) {
            const int n = col0 + wc + j * 8 + lc * 2;
            float b0 = 0.f, b1 = 0.f;
            if (bias) { b0 = bias[n]; b1 = bias[n + 1]; }
            if (r < M) {
                float2 v = make_float2(acc[i][j][0] + b0, acc[i][j][1] + b1);
                *reinterpret_cast<float2*>(&C[(size_t)r * N + n]) = v;
            }
            if (r + 8 < M) {
                float2 v = make_float2(acc[i][j][2] + b0, acc[i][j][3] + b1);
                *reinterpret_cast<float2*>(&C[(size_t)(r + 8) * N + n]) = v;
            }
        }
    }
}

// ===========================================================================
// Tensor-core windowed attention. One block per (b,h,window), 512 threads.
// ===========================================================================
#define MPAD   208
#define SSLD   132
#define KCLD   68
#define VCLD   72
#define SS_W   (MPAD * SSLD)
#define KC_W   (128 * KCLD)
#define VC_W   (128 * VCLD)
#define WA_SMEM ((SS_W + KC_W + VC_W + 3 * MPAD) * 4)

__global__ __launch_bounds__(512, 1) void win_attn_mma_kernel(
    const float* __restrict__ qkv, float* __restrict__ attn)
{
    extern __shared__ float sm[];
    float*    Ss  = sm;
    uint32_t* Su  = reinterpret_cast<uint32_t*>(sm);
    uint32_t* Kc  = reinterpret_cast<uint32_t*>(sm + SS_W);
    uint32_t* Vc  = Kc + KC_W;
    float*    msm = reinterpret_cast<float*>(Vc + VC_W);
    float*    lsm = msm + MPAD;
    float*    fs  = lsm + MPAD;

    const int w  = blockIdx.x;
    const int fi = w % NF;
    const int bh = w / NF;
    const int h  = bh % NHEAD;
    const int b  = bh / NHEAD;
    const int tid  = threadIdx.x;
    const int wid  = tid >> 5;
    const int lane = tid & 31;
    const int lr   = lane >> 2;
    const int lc   = lane & 3;

    const size_t base = (size_t)b * NTOK * QKVCOLS;
    const int qcol = h * DHEAD;
    const int kcol = DMODEL + h * DHEAD;
    const int vcol = 2 * DMODEL + h * DHEAD;

    for (int r = tid; r < MPAD; r += 512) { msm[r] = -1e30f; lsm[r] = 0.f; }

    uint32_t qf[8][4];
    const int r0 = wid * 16 + lr;
    const int r1 = r0 + 8;
    {
        const bool v0 = (wid < 13) && (r0 < NWIN);
        const bool v1 = (wid < 13) && (r1 < NWIN);
        const float* q0 = qkv + base + (size_t)(1 + fi * NWIN + r0) * QKVCOLS + qcol;
        const float* q1 = qkv + base + (size_t)(1 + fi * NWIN + r1) * QKVCOLS + qcol;
        #pragma unroll
        for (int ks = 0; ks < 8; ks++) {
            const int d0 = ks * 8 + lc;
            qf[ks][0] = v0 ? f2tf32(q0[d0]     * 0.125f) : 0u;
            qf[ks][1] = v1 ? f2tf32(q1[d0]     * 0.125f) : 0u;
            qf[ks][2] = v0 ? f2tf32(q0[d0 + 4] * 0.125f) : 0u;
            qf[ks][3] = v1 ? f2tf32(q1[d0 + 4] * 0.125f) : 0u;
        }
    }

    float O[8][4];
    #pragma unroll
    for (int dt = 0; dt < 8; dt++)
        #pragma unroll
        for (int q = 0; q < 4; q++) O[dt][q] = 0.f;

    for (int c = 0; c < 2; c++) {
        const int len    = (c == 0) ? 128 : (NKEY - 128);
        const int ntiles = (len + 7) >> 3;
        const int pl     = ntiles * 8;

        for (int idx = tid; idx < pl * 16; idx += 512) {
            const int kr = idx >> 4;
            const int d4 = (idx & 15) * 4;
            const int gk = c * 128 + kr;
            float4 kv = make_float4(0.f, 0.f, 0.f, 0.f), vv = kv;
            if (gk < NKEY) {
                const int tok = (gk == 0) ? 0 : (1 + fi * NWIN + (gk - 1));
                const float* rp = qkv + base + (size_t)tok * QKVCOLS;
                kv = *reinterpret_cast<const float4*>(rp + kcol + d4);
                vv = *reinterpret_cast<const float4*>(rp + vcol + d4);
            }
            uint32_t* kp = Kc + kr * KCLD + d4;
            kp[0] = f2tf32(kv.x); kp[1] = f2tf32(kv.y);
            kp[2] = f2tf32(kv.z); kp[3] = f2tf32(kv.w);
            uint32_t* vp = Vc + kr * VCLD + d4;
            vp[0] = f2tf32(vv.x); vp[1] = f2tf32(vv.y);
            vp[2] = f2tf32(vv.z); vp[3] = f2tf32(vv.w);
        }
        __syncthreads();

        if (wid < 13) {
            for (int nt = 0; nt < ntiles; nt++) {
                float a0 = 0.f, a1 = 0.f, a2 = 0.f, a3 = 0.f;
                const uint32_t* kb = Kc + (nt * 8 + lr) * KCLD + lc;
                #pragma unroll
                for (int ks = 0; ks < 8; ks++) {
                    uint32_t b0 = kb[ks * 8];
                    uint32_t b1 = kb[ks * 8 + 4];
                    mma_tf32(a0, a1, a2, a3,
                             qf[ks][0], qf[ks][1], qf[ks][2], qf[ks][3], b0, b1);
                }
                *reinterpret_cast<float2*>(&Ss[r0 * SSLD + nt * 8 + 2 * lc]) =
                    make_float2(a0, a1);
                *reinterpret_cast<float2*>(&Ss[r1 * SSLD + nt * 8 + 2 * lc]) =
                    make_float2(a2, a3);
            }
        }
        __syncthreads();

        if (tid < MPAD) {
            const int r = tid;
            float* srow = Ss + r * SSLD;
            const float mold = msm[r];
            float mc = mold;
            for (int j = 0; j < len; j++) mc = fmaxf(mc, srow[j]);
            const float f = __expf(mold - mc);
            float ls = 0.f;
            uint32_t* prow = Su + r * SSLD;
            for (int j = 0; j < pl; j++) {
                float p = (j < len) ? __expf(srow[j] - mc) : 0.f;
                ls += p;
                prow[j] = f2tf32(p);
            }
            msm[r] = mc;
            lsm[r] = lsm[r] * f + ls;
            fs[r]  = f;
        }
        __syncthreads();

        if (wid < 13) {
            const float f0 = fs[r0];
            const float f1 = fs[r1];
            #pragma unroll
            for (int dt = 0; dt < 8; dt++) {
                O[dt][0] *= f0; O[dt][1] *= f0;
                O[dt][2] *= f1; O[dt][3] *= f1;
            }
            for (int kt = 0; kt < ntiles; kt++) {
                const uint32_t pa0 = Su[r0 * SSLD + kt * 8 + lc];
                const uint32_t pa1 = Su[r1 * SSLD + kt * 8 + lc];
                const uint32_t pa2 = Su[r0 * SSLD + kt * 8 + lc + 4];
                const uint32_t pa3 = Su[r1 * SSLD + kt * 8 + lc + 4];
                const uint32_t* v0 = Vc + (kt * 8 + lc) * VCLD + lr;
                const uint32_t* v1 = Vc + (kt * 8 + lc + 4) * VCLD + lr;
                #pragma unroll
                for (int dt = 0; dt < 8; dt++) {
                    mma_tf32(O[dt][0], O[dt][1], O[dt][2], O[dt][3],
                             pa0, pa1, pa2, pa3, v0[dt * 8], v1[dt * 8]);
                }
            }
        }
        __syncthreads();
    }

    if (wid < 13) {
        const bool v0 = r0 < NWIN;
        const bool v1 = r1 < NWIN;
        const float inv0 = v0 ? (1.f / lsm[r0]) : 0.f;
        const float inv1 = v1 ? (1.f / lsm[r1]) : 0.f;
        float* o0 = attn + ((size_t)b * NTOK + 1 + fi * NWIN + r0) * DMODEL + h * DHEAD;
        float* o1 = attn + ((size_t)b * NTOK + 1 + fi * NWIN + r1) * DMODEL + h * DHEAD;
        #pragma unroll
        for (int dt = 0; dt < 8; dt++) {
            const int d = dt * 8 + 2 * lc;
            if (v0) *reinterpret_cast<float2*>(o0 + d) =
                make_float2(O[dt][0] * inv0, O[dt][1] * inv0);
            if (v1) *reinterpret_cast<float2*>(o1 + d) =
                make_float2(O[dt][2] * inv1, O[dt][3] * inv1);
        }
    }
}

// ---------------------------------------------------------------------------
// cls-token attention: one block per (b, h). Scalar fp32 (tiny).
// ---------------------------------------------------------------------------
__global__ __launch_bounds__(256) void cls_attn_kernel(
    const float* __restrict__ qkv, float* __restrict__ attn)
{
    __shared__ float sims[NTOK];
    __shared__ float qs[DHEAD];
    __shared__ float red[256];

    const int bh = blockIdx.x;
    const int h  = bh % NHEAD;
    const int b  = bh / NHEAD;
    const int tid = threadIdx.x;

    const size_t base = (size_t)b * NTOK * QKVCOLS;
    const int qcol = h * DHEAD;
    const int kcol = DMODEL + h * DHEAD;
    const int vcol = 2 * DMODEL + h * DHEAD;

    if (tid < DHEAD) qs[tid] = qkv[base + qcol + tid] * 0.125f;
    __syncthreads();

    for (int j = tid; j < NTOK; j += 256) {
        const float* kp = qkv + base + (size_t)j * QKVCOLS + kcol;
        float s = 0.f;
        #pragma unroll
        for (int d = 0; d < DHEAD; d++) s = fmaf(qs[d], kp[d], s);
        sims[j] = s;
    }
    __syncthreads();

    float m = -1e30f;
    for (int j = tid; j < NTOK; j += 256) m = fmaxf(m, sims[j]);
    red[tid] = m; __syncthreads();
    for (int s2 = 128; s2 > 0; s2 >>= 1) {
        if (tid < s2) red[tid] = fmaxf(red[tid], red[tid + s2]);
        __syncthreads();
    }
    m = red[0]; __syncthreads();

    float lsum = 0.f;
    for (int j = tid; j < NTOK; j += 256) {
        float p = __expf(sims[j] - m);
        sims[j] = p;
        lsum += p;
    }
    red[tid] = lsum; __syncthreads();
    for (int s2 = 128; s2 > 0; s2 >>= 1) {
        if (tid < s2) red[tid] += red[tid + s2];
        __syncthreads();
    }
    float inv = 1.f / red[0];
    __syncthreads();

    const int d  = tid & 63;
    const int jg = tid >> 6;
    float o = 0.f;
    for (int j = jg; j < NTOK; j += 4)
        o = fmaf(sims[j], qkv[base + (size_t)j * QKVCOLS + vcol + d], o);
    red[tid] = o; __syncthreads();
    if (jg == 0) {
        o = red[d] + red[64 + d] + red[128 + d] + red[192 + d];
        attn[(size_t)b * NTOK * DMODEL + h * DHEAD + d] = o * inv;
    }
}

// ---------------------------------------------------------------------------
extern "C" void kernel_launch(void* const* d_in, const int* in_sizes, int n_in,
                              void* d_out, int out_size)
{
    const float* x      = (const float*)d_in[0];
    const float* w_qkv  = (const float*)d_in[1];
    const float* w_proj = (const float*)d_in[2];
    const float* b_proj = (const float*)d_in[3];
    float* out = (float*)d_out;

    float* qkv  = nullptr;
    float* attn = nullptr;
    cudaGetSymbolAddress((void**)&qkv,  g_qkv);
    cudaGetSymbolAddress((void**)&attn, g_attn);

    cudaFuncSetAttribute(win_attn_mma_kernel,
                         cudaFuncAttributeMaxDynamicSharedMemorySize, WA_SMEM);

    // 1) qkv = x @ w_qkv   [25104 x 2304]
    {
        dim3 grid(QKVCOLS / 128, (MROWS + 127) / 128);
        mm_tf32_kernel<<<grid, 256>>>(x, w_qkv, qkv, nullptr, MROWS, QKVCOLS);
    }
    // 2) windowed attention (tensor cores)
    win_attn_mma_kernel<<<BATCH * NHEAD * NF, 512, WA_SMEM>>>(qkv, attn);
    // 3) cls attention
    cls_attn_kernel<<<BATCH * NHEAD, 256>>>(qkv, attn);
    // 4) out = attn @ w_proj + b_proj   [25104 x 768]
    {
        dim3 grid(DMODEL / 128, (MROWS + 127) / 128);
        mm_tf32_kernel<<<grid, 256>>>(attn, w_proj, out, b_proj, MROWS, DMODEL);
    }
}

// round 9
// speedup vs baseline: 2.8405x; 1.1307x over previous
#include <cuda_runtime.h>
#include <cuda_bf16.h>
#include <cstdint>

// Problem constants (fixed by setup_inputs)
#define BATCH   16
#define NTOK    1569          // 1 + 8*196
#define DMODEL  768
#define NHEAD   12
#define DHEAD   64
#define NF      8
#define NWIN    196
#define NKEY    197
#define MROWS   (BATCH * NTOK)      // 25104
#define QKVCOLS (3 * DMODEL)        // 2304

// Scratch (allocation-free rule: __device__ globals)
__device__ float g_qkv  [ (size_t)MROWS * QKVCOLS ];
__device__ float g_attn [ (size_t)MROWS * DMODEL  ];
__device__ float g_xtf  [ (size_t)MROWS * DMODEL  ];
__device__ float g_wqkv [ (size_t)DMODEL * QKVCOLS ];
__device__ float g_wproj[ (size_t)DMODEL * DMODEL  ];

__device__ __forceinline__ uint32_t f2tf32(float x) {
    uint32_t r;
    asm("cvt.rna.tf32.f32 %0, %1;" : "=r"(r) : "f"(x));
    return r;
}

__device__ __forceinline__ void mma_tf32(
    float& c0, float& c1, float& c2, float& c3,
    uint32_t a0, uint32_t a1, uint32_t a2, uint32_t a3,
    uint32_t b0, uint32_t b1)
{
    asm volatile(
        "mma.sync.aligned.m16n8k8.row.col.f32.tf32.tf32.f32 "
        "{%0,%1,%2,%3}, {%4,%5,%6,%7}, {%8,%9}, {%0,%1,%2,%3};"
        : "+f"(c0), "+f"(c1), "+f"(c2), "+f"(c3)
        : "r"(a0), "r"(a1), "r"(a2), "r"(a3), "r"(b0), "r"(b1));
}

__device__ __forceinline__ void cpa16(uint32_t dst, const void* src, bool pred) {
    int sz = pred ? 16 : 0;
    asm volatile("cp.async.cg.shared.global [%0], [%1], 16, %2;"
                 :: "r"(dst), "l"(src), "r"(sz));
}

// ---------------------------------------------------------------------------
// Pre-round fp32 -> tf32(RNA) bit-pattern, stored as float. Grid-stride float4.
// ---------------------------------------------------------------------------
__global__ __launch_bounds__(256) void cvt_tf32_kernel(
    const float* __restrict__ in, float* __restrict__ out, int n4)
{
    for (int i = blockIdx.x * blockDim.x + threadIdx.x; i < n4;
         i += gridDim.x * blockDim.x) {
        float4 v = reinterpret_cast<const float4*>(in)[i];
        uint4 o;
        o.x = f2tf32(v.x); o.y = f2tf32(v.y);
        o.z = f2tf32(v.z); o.w = f2tf32(v.w);
        reinterpret_cast<uint4*>(out)[i] = o;
    }
}

// ===========================================================================
// TF32 mma.sync GEMM with cp.async 4-stage pipeline + ldmatrix A fragments.
// Inputs A,B must be PRE-ROUNDED to tf32 bit patterns.
// CTA 128x128, BK=16; A tile [128m][16k] stride 20 words (80B, conflict-free
// ldmatrix); B tile [16k][128n] stride 136 words (conflict-free LDS.32).
// ===========================================================================
#define GK     768
#define BK     16
#define NC     (GK / BK)       // 48
#define AS_W   (128 * 20)      // 2560 words / stage
#define BS_W   (BK * 136)      // 2176 words / stage
#define STW    (AS_W + BS_W)   // 4736 words / stage
#define STAGES 4
#define MM_SMEM (STAGES * STW * 4)   // 75776 bytes

__global__ __launch_bounds__(256, 2) void mm_tf32_kernel(
    const float* __restrict__ A, const float* __restrict__ B,
    float* __restrict__ C, const float* __restrict__ bias, int M, int N)
{
    extern __shared__ float sm[];
    const uint32_t smem_u = (uint32_t)__cvta_generic_to_shared(sm);

    const int tid  = threadIdx.x;
    const int wid  = tid >> 5;
    const int lane = tid & 31;
    const int lr   = lane >> 2;
    const int lc   = lane & 3;
    const int wr   = (wid & 1) * 64;
    const int wc   = (wid >> 1) * 32;
    const int row0 = blockIdx.y * 128;
    const int col0 = blockIdx.x * 128;

    // cp.async mappings (2 chunks each for A and B per thread per stage)
    const int am0 = tid >> 1;                  // ids tid, tid+256 -> m = id>>2
    // generic: id -> m = id>>2, ch = id&3   (A: 512 chunks)
    //          id -> k = id>>5, cn = id&31  (B: 512 chunks)

    // ldmatrix per-thread address pieces
    const int arow = wr + (lane & 15);         // row within CTA tile
    const int koff = (lane >> 4) * 4;          // 0 or 4

    float acc[4][4][4];
    #pragma unroll
    for (int i = 0; i < 4; i++)
        #pragma unroll
        for (int j = 0; j < 4; j++)
            #pragma unroll
            for (int q = 0; q < 4; q++) acc[i][j][q] = 0.f;

    auto issue = [&](int c, int s) {
        const uint32_t ab = smem_u + (uint32_t)(s * STW) * 4u;
        const uint32_t bb = ab + AS_W * 4u;
        const int k0 = c * BK;
        #pragma unroll
        for (int t2 = 0; t2 < 2; t2++) {
            const int ida = tid + 256 * t2;
            const int m   = ida >> 2;
            const int ch  = ida & 3;
            cpa16(ab + (uint32_t)(m * 20 + ch * 4) * 4u,
                  A + (size_t)(row0 + m) * GK + k0 + ch * 4,
                  (row0 + m) < M);
            const int k  = ida >> 5;
            const int cn = ida & 31;
            cpa16(bb + (uint32_t)(k * 136 + cn * 4) * 4u,
                  B + (size_t)(k0 + k) * N + col0 + cn * 4, true);
        }
        asm volatile("cp.async.commit_group;" ::: "memory");
    };

    issue(0, 0); issue(1, 1); issue(2, 2);

    for (int c = 0; c < NC; c++) {
        const int s = c & 3;
        asm volatile("cp.async.wait_group 2;" ::: "memory");
        __syncthreads();
        if (c + 3 < NC) issue(c + 3, (c + 3) & 3);

        const uint32_t ab = smem_u + (uint32_t)(s * STW) * 4u;
        const float*   Bsf = sm + s * STW + AS_W;

        #pragma unroll
        for (int kg = 0; kg < 2; kg++) {
            const int kb = kg * 8;
            uint32_t af[4][4];
            #pragma unroll
            for (int i = 0; i < 4; i++) {
                const uint32_t addr =
                    ab + (uint32_t)((arow + i * 16) * 20 + kb + koff) * 4u;
                asm volatile(
                    "ldmatrix.sync.aligned.m8n8.x4.shared.b16 {%0,%1,%2,%3}, [%4];"
                    : "=r"(af[i][0]), "=r"(af[i][1]), "=r"(af[i][2]), "=r"(af[i][3])
                    : "r"(addr));
            }
            uint32_t bf[4][2];
            #pragma unroll
            for (int j = 0; j < 4; j++) {
                const int n = wc + j * 8 + lr;
                bf[j][0] = __float_as_uint(Bsf[(kb + lc) * 136 + n]);
                bf[j][1] = __float_as_uint(Bsf[(kb + lc + 4) * 136 + n]);
            }
            #pragma unroll
            for (int i = 0; i < 4; i++)
                #pragma unroll
                for (int j = 0; j < 4; j++)
                    mma_tf32(acc[i][j][0], acc[i][j][1], acc[i][j][2], acc[i][j][3],
                             af[i][0], af[i][1], af[i][2], af[i][3],
                             bf[j][0], bf[j][1]);
        }
    }
    asm volatile("cp.async.wait_group 0;" ::: "memory");

    #pragma unroll
    for (int i = 0; i < 4; i++) {
        const int r = row0 + wr + i * 16 + lr;
        #pragma unroll
        for (int j = 0; j < 4; j++) {
            const int n = col0 + wc + j * 8 + lc * 2;
            float b0 = 0.f, b1 = 0.f;
            if (bias) { b0 = bias[n]; b1 = bias[n + 1]; }
            if (r < M) {
                float2 v = make_float2(acc[i][j][0] + b0, acc[i][j][1] + b1);
                *reinterpret_cast<float2*>(&C[(size_t)r * N + n]) = v;
            }
            if (r + 8 < M) {
                float2 v = make_float2(acc[i][j][2] + b0, acc[i][j][3] + b1);
                *reinterpret_cast<float2*>(&C[(size_t)(r + 8) * N + n]) = v;
            }
        }
    }
}

// ===========================================================================
// Tensor-core windowed attention. One block per (b,h,window), 512 threads.
// Output stores are tf32-pre-rounded (feeds proj GEMM A input).
// ===========================================================================
#define MPAD   208
#define SSLD   132
#define KCLD   68
#define VCLD   72
#define SS_W   (MPAD * SSLD)
#define KC_W   (128 * KCLD)
#define VC_W   (128 * VCLD)
#define WA_SMEM ((SS_W + KC_W + VC_W + 3 * MPAD) * 4)

__global__ __launch_bounds__(512, 1) void win_attn_mma_kernel(
    const float* __restrict__ qkv, float* __restrict__ attn)
{
    extern __shared__ float sm[];
    float*    Ss  = sm;
    uint32_t* Su  = reinterpret_cast<uint32_t*>(sm);
    uint32_t* Kc  = reinterpret_cast<uint32_t*>(sm + SS_W);
    uint32_t* Vc  = Kc + KC_W;
    float*    msm = reinterpret_cast<float*>(Vc + VC_W);
    float*    lsm = msm + MPAD;
    float*    fs  = lsm + MPAD;

    const int w  = blockIdx.x;
    const int fi = w % NF;
    const int bh = w / NF;
    const int h  = bh % NHEAD;
    const int b  = bh / NHEAD;
    const int tid  = threadIdx.x;
    const int wid  = tid >> 5;
    const int lane = tid & 31;
    const int lr   = lane >> 2;
    const int lc   = lane & 3;

    const size_t base = (size_t)b * NTOK * QKVCOLS;
    const int qcol = h * DHEAD;
    const int kcol = DMODEL + h * DHEAD;
    const int vcol = 2 * DMODEL + h * DHEAD;

    for (int r = tid; r < MPAD; r += 512) { msm[r] = -1e30f; lsm[r] = 0.f; }

    uint32_t qf[8][4];
    const int r0 = wid * 16 + lr;
    const int r1 = r0 + 8;
    {
        const bool v0 = (wid < 13) && (r0 < NWIN);
        const bool v1 = (wid < 13) && (r1 < NWIN);
        const float* q0 = qkv + base + (size_t)(1 + fi * NWIN + r0) * QKVCOLS + qcol;
        const float* q1 = qkv + base + (size_t)(1 + fi * NWIN + r1) * QKVCOLS + qcol;
        #pragma unroll
        for (int ks = 0; ks < 8; ks++) {
            const int d0 = ks * 8 + lc;
            qf[ks][0] = v0 ? f2tf32(q0[d0]     * 0.125f) : 0u;
            qf[ks][1] = v1 ? f2tf32(q1[d0]     * 0.125f) : 0u;
            qf[ks][2] = v0 ? f2tf32(q0[d0 + 4] * 0.125f) : 0u;
            qf[ks][3] = v1 ? f2tf32(q1[d0 + 4] * 0.125f) : 0u;
        }
    }

    float O[8][4];
    #pragma unroll
    for (int dt = 0; dt < 8; dt++)
        #pragma unroll
        for (int q = 0; q < 4; q++) O[dt][q] = 0.f;

    for (int c = 0; c < 2; c++) {
        const int len    = (c == 0) ? 128 : (NKEY - 128);
        const int ntiles = (len + 7) >> 3;
        const int pl     = ntiles * 8;

        for (int idx = tid; idx < pl * 16; idx += 512) {
            const int kr = idx >> 4;
            const int d4 = (idx & 15) * 4;
            const int gk = c * 128 + kr;
            float4 kv = make_float4(0.f, 0.f, 0.f, 0.f), vv = kv;
            if (gk < NKEY) {
                const int tok = (gk == 0) ? 0 : (1 + fi * NWIN + (gk - 1));
                const float* rp = qkv + base + (size_t)tok * QKVCOLS;
                kv = *reinterpret_cast<const float4*>(rp + kcol + d4);
                vv = *reinterpret_cast<const float4*>(rp + vcol + d4);
            }
            uint32_t* kp = Kc + kr * KCLD + d4;
            kp[0] = f2tf32(kv.x); kp[1] = f2tf32(kv.y);
            kp[2] = f2tf32(kv.z); kp[3] = f2tf32(kv.w);
            uint32_t* vp = Vc + kr * VCLD + d4;
            vp[0] = f2tf32(vv.x); vp[1] = f2tf32(vv.y);
            vp[2] = f2tf32(vv.z); vp[3] = f2tf32(vv.w);
        }
        __syncthreads();

        if (wid < 13) {
            for (int nt = 0; nt < ntiles; nt++) {
                float a0 = 0.f, a1 = 0.f, a2 = 0.f, a3 = 0.f;
                const uint32_t* kb = Kc + (nt * 8 + lr) * KCLD + lc;
                #pragma unroll
                for (int ks = 0; ks < 8; ks++) {
                    uint32_t b0 = kb[ks * 8];
                    uint32_t b1 = kb[ks * 8 + 4];
                    mma_tf32(a0, a1, a2, a3,
                             qf[ks][0], qf[ks][1], qf[ks][2], qf[ks][3], b0, b1);
                }
                *reinterpret_cast<float2*>(&Ss[r0 * SSLD + nt * 8 + 2 * lc]) =
                    make_float2(a0, a1);
                *reinterpret_cast<float2*>(&Ss[r1 * SSLD + nt * 8 + 2 * lc]) =
                    make_float2(a2, a3);
            }
        }
        __syncthreads();

        if (tid < MPAD) {
            const int r = tid;
            float* srow = Ss + r * SSLD;
            const float mold = msm[r];
            float mc = mold;
            for (int j = 0; j < len; j++) mc = fmaxf(mc, srow[j]);
            const float f = __expf(mold - mc);
            float ls = 0.f;
            uint32_t* prow = Su + r * SSLD;
            for (int j = 0; j < pl; j++) {
                float p = (j < len) ? __expf(srow[j] - mc) : 0.f;
                ls += p;
                prow[j] = f2tf32(p);
            }
            msm[r] = mc;
            lsm[r] = lsm[r] * f + ls;
            fs[r]  = f;
        }
        __syncthreads();

        if (wid < 13) {
            const float f0 = fs[r0];
            const float f1 = fs[r1];
            #pragma unroll
            for (int dt = 0; dt < 8; dt++) {
                O[dt][0] *= f0; O[dt][1] *= f0;
                O[dt][2] *= f1; O[dt][3] *= f1;
            }
            for (int kt = 0; kt < ntiles; kt++) {
                const uint32_t pa0 = Su[r0 * SSLD + kt * 8 + lc];
                const uint32_t pa1 = Su[r1 * SSLD + kt * 8 + lc];
                const uint32_t pa2 = Su[r0 * SSLD + kt * 8 + lc + 4];
                const uint32_t pa3 = Su[r1 * SSLD + kt * 8 + lc + 4];
                const uint32_t* v0 = Vc + (kt * 8 + lc) * VCLD + lr;
                const uint32_t* v1 = Vc + (kt * 8 + lc + 4) * VCLD + lr;
                #pragma unroll
                for (int dt = 0; dt < 8; dt++) {
                    mma_tf32(O[dt][0], O[dt][1], O[dt][2], O[dt][3],
                             pa0, pa1, pa2, pa3, v0[dt * 8], v1[dt * 8]);
                }
            }
        }
        __syncthreads();
    }

    if (wid < 13) {
        const bool v0 = r0 < NWIN;
        const bool v1 = r1 < NWIN;
        const float inv0 = v0 ? (1.f / lsm[r0]) : 0.f;
        const float inv1 = v1 ? (1.f / lsm[r1]) : 0.f;
        float* o0 = attn + ((size_t)b * NTOK + 1 + fi * NWIN + r0) * DMODEL + h * DHEAD;
        float* o1 = attn + ((size_t)b * NTOK + 1 + fi * NWIN + r1) * DMODEL + h * DHEAD;
        #pragma unroll
        for (int dt = 0; dt < 8; dt++) {
            const int d = dt * 8 + 2 * lc;
            if (v0) *reinterpret_cast<float2*>(o0 + d) = make_float2(
                __uint_as_float(f2tf32(O[dt][0] * inv0)),
                __uint_as_float(f2tf32(O[dt][1] * inv0)));
            if (v1) *reinterpret_cast<float2*>(o1 + d) = make_float2(
                __uint_as_float(f2tf32(O[dt][2] * inv1)),
                __uint_as_float(f2tf32(O[dt][3] * inv1)));
        }
    }
}

// ---------------------------------------------------------------------------
// cls-token attention: one block per (b, h). Output tf32-pre-rounded.
// ---------------------------------------------------------------------------
__global__ __launch_bounds__(256) void cls_attn_kernel(
    const float* __restrict__ qkv, float* __restrict__ attn)
{
    __shared__ float sims[NTOK];
    __shared__ float qs[DHEAD];
    __shared__ float red[256];

    const int bh = blockIdx.x;
    const int h  = bh % NHEAD;
    const int b  = bh / NHEAD;
    const int tid = threadIdx.x;

    const size_t base = (size_t)b * NTOK * QKVCOLS;
    const int qcol = h * DHEAD;
    const int kcol = DMODEL + h * DHEAD;
    const int vcol = 2 * DMODEL + h * DHEAD;

    if (tid < DHEAD) qs[tid] = qkv[base + qcol + tid] * 0.125f;
    __syncthreads();

    for (int j = tid; j < NTOK; j += 256) {
        const float* kp = qkv + base + (size_t)j * QKVCOLS + kcol;
        float s = 0.f;
        #pragma unroll
        for (int d = 0; d < DHEAD; d++) s = fmaf(qs[d], kp[d], s);
        sims[j] = s;
    }
    __syncthreads();

    float m = -1e30f;
    for (int j = tid; j < NTOK; j += 256) m = fmaxf(m, sims[j]);
    red[tid] = m; __syncthreads();
    for (int s2 = 128; s2 > 0; s2 >>= 1) {
        if (tid < s2) red[tid] = fmaxf(red[tid], red[tid + s2]);
        __syncthreads();
    }
    m = red[0]; __syncthreads();

    float lsum = 0.f;
    for (int j = tid; j < NTOK; j += 256) {
        float p = __expf(sims[j] - m);
        sims[j] = p;
        lsum += p;
    }
    red[tid] = lsum; __syncthreads();
    for (int s2 = 128; s2 > 0; s2 >>= 1) {
        if (tid < s2) red[tid] += red[tid + s2];
        __syncthreads();
    }
    float inv = 1.f / red[0];
    __syncthreads();

    const int d  = tid & 63;
    const int jg = tid >> 6;
    float o = 0.f;
    for (int j = jg; j < NTOK; j += 4)
        o = fmaf(sims[j], qkv[base + (size_t)j * QKVCOLS + vcol + d], o);
    red[tid] = o; __syncthreads();
    if (jg == 0) {
        o = red[d] + red[64 + d] + red[128 + d] + red[192 + d];
        attn[(size_t)b * NTOK * DMODEL + h * DHEAD + d] =
            __uint_as_float(f2tf32(o * inv));
    }
}

// ---------------------------------------------------------------------------
extern "C" void kernel_launch(void* const* d_in, const int* in_sizes, int n_in,
                              void* d_out, int out_size)
{
    const float* x      = (const float*)d_in[0];
    const float* w_qkv  = (const float*)d_in[1];
    const float* w_proj = (const float*)d_in[2];
    const float* b_proj = (const float*)d_in[3];
    float* out = (float*)d_out;

    float* qkv   = nullptr;
    float* attn  = nullptr;
    float* xtf   = nullptr;
    float* wqkv  = nullptr;
    float* wproj = nullptr;
    cudaGetSymbolAddress((void**)&qkv,   g_qkv);
    cudaGetSymbolAddress((void**)&attn,  g_attn);
    cudaGetSymbolAddress((void**)&xtf,   g_xtf);
    cudaGetSymbolAddress((void**)&wqkv,  g_wqkv);
    cudaGetSymbolAddress((void**)&wproj, g_wproj);

    cudaFuncSetAttribute(mm_tf32_kernel,
                         cudaFuncAttributeMaxDynamicSharedMemorySize, MM_SMEM);
    cudaFuncSetAttribute(win_attn_mma_kernel,
                         cudaFuncAttributeMaxDynamicSharedMemorySize, WA_SMEM);

    // 0) pre-round inputs to tf32
    cvt_tf32_kernel<<<4096, 256>>>(x,      xtf,   MROWS * DMODEL / 4);
    cvt_tf32_kernel<<<1024, 256>>>(w_qkv,  wqkv,  DMODEL * QKVCOLS / 4);
    cvt_tf32_kernel<<<512,  256>>>(w_proj, wproj, DMODEL * DMODEL / 4);

    // 1) qkv = x @ w_qkv   [25104 x 2304]
    {
        dim3 grid(QKVCOLS / 128, (MROWS + 127) / 128);
        mm_tf32_kernel<<<grid, 256, MM_SMEM>>>(xtf, wqkv, qkv, nullptr, MROWS, QKVCOLS);
    }
    // 2) windowed attention (tensor cores)
    win_attn_mma_kernel<<<BATCH * NHEAD * NF, 512, WA_SMEM>>>(qkv, attn);
    // 3) cls attention
    cls_attn_kernel<<<BATCH * NHEAD, 256>>>(qkv, attn);
    // 4) out = attn @ w_proj + b_proj   [25104 x 768]
    {
        dim3 grid(DMODEL / 128, (MROWS + 127) / 128);
        mm_tf32_kernel<<<grid, 256, MM_SMEM>>>(attn, wproj, out, b_proj, MROWS, DMODEL);
    }
}

// round 14
// speedup vs baseline: 3.0828x; 1.0853x over previous
#include <cuda_runtime.h>
#include <cuda_bf16.h>
#include <cstdint>

// Problem constants (fixed by setup_inputs)
#define BATCH   16
#define NTOK    1569          // 1 + 8*196
#define DMODEL  768
#define NHEAD   12
#define DHEAD   64
#define NF      8
#define NWIN    196
#define NKEY    197
#define MROWS   (BATCH * NTOK)      // 25104
#define QKVCOLS (3 * DMODEL)        // 2304

// Scratch (allocation-free rule: __device__ globals)
__device__ float g_qkv  [ (size_t)MROWS * QKVCOLS ];
__device__ float g_attn [ (size_t)MROWS * DMODEL  ];
__device__ float g_xtf  [ (size_t)MROWS * DMODEL  ];
__device__ float g_wqkv [ (size_t)DMODEL * QKVCOLS ];
__device__ float g_wproj[ (size_t)DMODEL * DMODEL  ];

__device__ __forceinline__ uint32_t f2tf32(float x) {
    uint32_t r;
    asm("cvt.rna.tf32.f32 %0, %1;" : "=r"(r) : "f"(x));
    return r;
}

__device__ __forceinline__ void mma_tf32(
    float& c0, float& c1, float& c2, float& c3,
    uint32_t a0, uint32_t a1, uint32_t a2, uint32_t a3,
    uint32_t b0, uint32_t b1)
{
    asm volatile(
        "mma.sync.aligned.m16n8k8.row.col.f32.tf32.tf32.f32 "
        "{%0,%1,%2,%3}, {%4,%5,%6,%7}, {%8,%9}, {%0,%1,%2,%3};"
        : "+f"(c0), "+f"(c1), "+f"(c2), "+f"(c3)
        : "r"(a0), "r"(a1), "r"(a2), "r"(a3), "r"(b0), "r"(b1));
}

__device__ __forceinline__ void cpa16(uint32_t dst, const void* src, bool pred) {
    int sz = pred ? 16 : 0;
    asm volatile("cp.async.cg.shared.global [%0], [%1], 16, %2;"
                 :: "r"(dst), "l"(src), "r"(sz));
}

// ---------------------------------------------------------------------------
// Pre-round fp32 -> tf32(RNA) bit-pattern, stored as float.
// ---------------------------------------------------------------------------
__global__ __launch_bounds__(256) void cvt_tf32_kernel(
    const float* __restrict__ in, float* __restrict__ out, int n4)
{
    for (int i = blockIdx.x * blockDim.x + threadIdx.x; i < n4;
         i += gridDim.x * blockDim.x) {
        float4 v = reinterpret_cast<const float4*>(in)[i];
        uint4 o;
        o.x = f2tf32(v.x); o.y = f2tf32(v.y);
        o.z = f2tf32(v.z); o.w = f2tf32(v.w);
        reinterpret_cast<uint4*>(out)[i] = o;
    }
}

// ===========================================================================
// TF32 mma.sync GEMM with cp.async 4-stage pipeline + ldmatrix A fragments.
// ===========================================================================
#define GK     768
#define BK     16
#define NC     (GK / BK)       // 48
#define AS_W   (128 * 20)
#define BS_W   (BK * 136)
#define STW    (AS_W + BS_W)
#define STAGES 4
#define MM_SMEM (STAGES * STW * 4)

__global__ __launch_bounds__(256, 2) void mm_tf32_kernel(
    const float* __restrict__ A, const float* __restrict__ B,
    float* __restrict__ C, const float* __restrict__ bias, int M, int N)
{
    extern __shared__ float sm[];
    const uint32_t smem_u = (uint32_t)__cvta_generic_to_shared(sm);

    const int tid  = threadIdx.x;
    const int wid  = tid >> 5;
    const int lane = tid & 31;
    const int lr   = lane >> 2;
    const int lc   = lane & 3;
    const int wr   = (wid & 1) * 64;
    const int wc   = (wid >> 1) * 32;
    const int row0 = blockIdx.y * 128;
    const int col0 = blockIdx.x * 128;

    const int arow = wr + (lane & 15);
    const int koff = (lane >> 4) * 4;

    float acc[4][4][4];
    #pragma unroll
    for (int i = 0; i < 4; i++)
        #pragma unroll
        for (int j = 0; j < 4; j++)
            #pragma unroll
            for (int q = 0; q < 4; q++) acc[i][j][q] = 0.f;

    auto issue = [&](int c, int s) {
        const uint32_t ab = smem_u + (uint32_t)(s * STW) * 4u;
        const uint32_t bb = ab + AS_W * 4u;
        const int k0 = c * BK;
        #pragma unroll
        for (int t2 = 0; t2 < 2; t2++) {
            const int ida = tid + 256 * t2;
            const int m   = ida >> 2;
            const int ch  = ida & 3;
            cpa16(ab + (uint32_t)(m * 20 + ch * 4) * 4u,
                  A + (size_t)(row0 + m) * GK + k0 + ch * 4,
                  (row0 + m) < M);
            const int k  = ida >> 5;
            const int cn = ida & 31;
            cpa16(bb + (uint32_t)(k * 136 + cn * 4) * 4u,
                  B + (size_t)(k0 + k) * N + col0 + cn * 4, true);
        }
        asm volatile("cp.async.commit_group;" ::: "memory");
    };

    issue(0, 0); issue(1, 1); issue(2, 2);

    for (int c = 0; c < NC; c++) {
        const int s = c & 3;
        asm volatile("cp.async.wait_group 2;" ::: "memory");
        __syncthreads();
        if (c + 3 < NC) issue(c + 3, (c + 3) & 3);

        const uint32_t ab = smem_u + (uint32_t)(s * STW) * 4u;
        const float*   Bsf = sm + s * STW + AS_W;

        #pragma unroll
        for (int kg = 0; kg < 2; kg++) {
            const int kb = kg * 8;
            uint32_t af[4][4];
            #pragma unroll
            for (int i = 0; i < 4; i++) {
                const uint32_t addr =
                    ab + (uint32_t)((arow + i * 16) * 20 + kb + koff) * 4u;
                asm volatile(
                    "ldmatrix.sync.aligned.m8n8.x4.shared.b16 {%0,%1,%2,%3}, [%4];"
                    : "=r"(af[i][0]), "=r"(af[i][1]), "=r"(af[i][2]), "=r"(af[i][3])
                    : "r"(addr));
            }
            uint32_t bf[4][2];
            #pragma unroll
            for (int j = 0; j < 4; j++) {
                const int n = wc + j * 8 + lr;
                bf[j][0] = __float_as_uint(Bsf[(kb + lc) * 136 + n]);
                bf[j][1] = __float_as_uint(Bsf[(kb + lc + 4) * 136 + n]);
            }
            #pragma unroll
            for (int i = 0; i < 4; i++)
                #pragma unroll
                for (int j = 0; j < 4; j++)
                    mma_tf32(acc[i][j][0], acc[i][j][1], acc[i][j][2], acc[i][j][3],
                             af[i][0], af[i][1], af[i][2], af[i][3],
                             bf[j][0], bf[j][1]);
        }
    }
    asm volatile("cp.async.wait_group 0;" ::: "memory");

    #pragma unroll
    for (int i = 0; i < 4; i++) {
        const int r = row0 + wr + i * 16 + lr;
        #pragma unroll
        for (int j = 0; j < 4; j++) {
            const int n = col0 + wc + j * 8 + lc * 2;
            float b0 = 0.f, b1 = 0.f;
            if (bias) { b0 = bias[n]; b1 = bias[n + 1]; }
            if (r < M) {
                float2 v = make_float2(acc[i][j][0] + b0, acc[i][j][1] + b1);
                *reinterpret_cast<float2*>(&C[(size_t)r * N + n]) = v;
            }
            if (r + 8 < M) {
                float2 v = make_float2(acc[i][j][2] + b0, acc[i][j][3] + b1);
                *reinterpret_cast<float2*>(&C[(size_t)(r + 8) * N + n]) = v;
            }
        }
    }
}

// ===========================================================================
// Flash-style windowed attention, register-resident softmax.
// One block per (b,h,window), 512 threads, 13 mma warps (16-row tiles).
// Keys chunked by 64 (chunks: 64,64,64,5). K/V in 36KB static smem.
// ===========================================================================
#define KCH  64
#define KLD  68      // K row stride (words): lr*68+lc mod 32 conflict-free
#define VLD  72      // V row stride: lc*72+lr mod 32 conflict-free

__global__ __launch_bounds__(512, 1) void win_attn_mma_kernel(
    const float* __restrict__ qkv, float* __restrict__ attn)
{
    __shared__ uint32_t Kc[KCH * KLD];
    __shared__ uint32_t Vc[KCH * VLD];

    const int w  = blockIdx.x;
    const int fi = w % NF;
    const int bh = w / NF;
    const int h  = bh % NHEAD;
    const int b  = bh / NHEAD;
    const int tid  = threadIdx.x;
    const int wid  = tid >> 5;
    const int lane = tid & 31;
    const int lr   = lane >> 2;
    const int lc   = lane & 3;

    const size_t base = (size_t)b * NTOK * QKVCOLS;
    const int qcol = h * DHEAD;
    const int kcol = DMODEL + h * DHEAD;
    const int vcol = 2 * DMODEL + h * DHEAD;

    // Q fragments: warp wid owns rows [16*wid, 16*wid+16)
    uint32_t qf[8][4];
    const int r0 = wid * 16 + lr;
    const int r1 = r0 + 8;
    const bool v0 = (wid < 13) && (r0 < NWIN);
    const bool v1 = (wid < 13) && (r1 < NWIN);
    {
        const float* q0 = qkv + base + (size_t)(1 + fi * NWIN + r0) * QKVCOLS + qcol;
        const float* q1 = qkv + base + (size_t)(1 + fi * NWIN + r1) * QKVCOLS + qcol;
        #pragma unroll
        for (int ks = 0; ks < 8; ks++) {
            const int d0 = ks * 8 + lc;
            qf[ks][0] = v0 ? f2tf32(q0[d0]     * 0.125f) : 0u;
            qf[ks][1] = v1 ? f2tf32(q1[d0]     * 0.125f) : 0u;
            qf[ks][2] = v0 ? f2tf32(q0[d0 + 4] * 0.125f) : 0u;
            qf[ks][3] = v1 ? f2tf32(q1[d0 + 4] * 0.125f) : 0u;
        }
    }

    float O[8][4];
    #pragma unroll
    for (int dt = 0; dt < 8; dt++)
        #pragma unroll
        for (int q = 0; q < 4; q++) O[dt][q] = 0.f;
    float m0 = -1e30f, m1 = -1e30f, l0 = 0.f, l1 = 0.f;

    const int src1 = lr * 4 + (lc >> 1);
    const int src2 = src1 + 2;
    const bool hi  = lc & 1;

    #pragma unroll 1
    for (int c = 0; c < 4; c++) {
        const int kb0 = c * KCH;
        const int len = min(KCH, NKEY - kb0);        // 64,64,64,5
        const int NT  = (len + 7) >> 3;              // 8,8,8,1

        __syncthreads();    // previous chunk's smem readers done
        for (int idx = tid; idx < KCH * 16; idx += 512) {
            const int kr = idx >> 4;
            const int d4 = (idx & 15) * 4;
            const int gk = kb0 + kr;
            float4 kv = make_float4(0.f, 0.f, 0.f, 0.f), vv = kv;
            if (gk < NKEY) {
                const int tok = (gk == 0) ? 0 : (1 + fi * NWIN + (gk - 1));
                const float* rp = qkv + base + (size_t)tok * QKVCOLS;
                kv = *reinterpret_cast<const float4*>(rp + kcol + d4);
                vv = *reinterpret_cast<const float4*>(rp + vcol + d4);
            }
            uint32_t* kp = Kc + kr * KLD + d4;
            kp[0] = f2tf32(kv.x); kp[1] = f2tf32(kv.y);
            kp[2] = f2tf32(kv.z); kp[3] = f2tf32(kv.w);
            uint32_t* vp = Vc + kr * VLD + d4;
            vp[0] = f2tf32(vv.x); vp[1] = f2tf32(vv.y);
            vp[2] = f2tf32(vv.z); vp[3] = f2tf32(vv.w);
        }
        __syncthreads();

        if (wid < 13) {
            // ---- S = Q @ K^T (register fragments) ----
            float S[8][4];
            #pragma unroll
            for (int nt = 0; nt < 8; nt++) {
                if (nt >= NT) break;
                float a0 = 0.f, a1 = 0.f, a2 = 0.f, a3 = 0.f;
                const uint32_t* kp = Kc + (nt * 8 + lr) * KLD + lc;
                #pragma unroll
                for (int ks = 0; ks < 8; ks++)
                    mma_tf32(a0, a1, a2, a3,
                             qf[ks][0], qf[ks][1], qf[ks][2], qf[ks][3],
                             kp[ks * 8], kp[ks * 8 + 4]);
                S[nt][0] = a0; S[nt][1] = a1; S[nt][2] = a2; S[nt][3] = a3;
            }

            // ---- tail mask ----
            if (len < KCH) {
                #pragma unroll
                for (int nt = 0; nt < 8; nt++) {
                    if (nt >= NT) break;
                    const int cc = nt * 8 + 2 * lc;
                    if (cc     >= len) { S[nt][0] = -1e30f; S[nt][2] = -1e30f; }
                    if (cc + 1 >= len) { S[nt][1] = -1e30f; S[nt][3] = -1e30f; }
                }
            }

            // ---- row max (quad butterfly) ----
            float cm0 = -1e30f, cm1 = -1e30f;
            #pragma unroll
            for (int nt = 0; nt < 8; nt++) {
                if (nt >= NT) break;
                cm0 = fmaxf(cm0, fmaxf(S[nt][0], S[nt][1]));
                cm1 = fmaxf(cm1, fmaxf(S[nt][2], S[nt][3]));
            }
            cm0 = fmaxf(cm0, __shfl_xor_sync(0xffffffff, cm0, 1));
            cm0 = fmaxf(cm0, __shfl_xor_sync(0xffffffff, cm0, 2));
            cm1 = fmaxf(cm1, __shfl_xor_sync(0xffffffff, cm1, 1));
            cm1 = fmaxf(cm1, __shfl_xor_sync(0xffffffff, cm1, 2));
            const float nm0 = fmaxf(m0, cm0);
            const float nm1 = fmaxf(m1, cm1);
            const float f0 = __expf(m0 - nm0);
            const float f1 = __expf(m1 - nm1);
            m0 = nm0; m1 = nm1;

            // ---- exp + row sum ----
            float cl0 = 0.f, cl1 = 0.f;
            #pragma unroll
            for (int nt = 0; nt < 8; nt++) {
                if (nt >= NT) break;
                S[nt][0] = __expf(S[nt][0] - m0);
                S[nt][1] = __expf(S[nt][1] - m0);
                S[nt][2] = __expf(S[nt][2] - m1);
                S[nt][3] = __expf(S[nt][3] - m1);
                cl0 += S[nt][0] + S[nt][1];
                cl1 += S[nt][2] + S[nt][3];
            }
            cl0 += __shfl_xor_sync(0xffffffff, cl0, 1);
            cl0 += __shfl_xor_sync(0xffffffff, cl0, 2);
            cl1 += __shfl_xor_sync(0xffffffff, cl1, 1);
            cl1 += __shfl_xor_sync(0xffffffff, cl1, 2);
            l0 = l0 * f0 + cl0;
            l1 = l1 * f1 + cl1;

            // ---- rescale O ----
            #pragma unroll
            for (int dt = 0; dt < 8; dt++) {
                O[dt][0] *= f0; O[dt][1] *= f0;
                O[dt][2] *= f1; O[dt][3] *= f1;
            }

            // ---- O += P @ V (P A-frags via quad shuffles) ----
            #pragma unroll
            for (int kt = 0; kt < 8; kt++) {
                if (kt >= NT) break;
                const float x00 = __shfl_sync(0xffffffff, S[kt][0], src1);
                const float x01 = __shfl_sync(0xffffffff, S[kt][1], src1);
                const float x10 = __shfl_sync(0xffffffff, S[kt][2], src1);
                const float x11 = __shfl_sync(0xffffffff, S[kt][3], src1);
                const float y00 = __shfl_sync(0xffffffff, S[kt][0], src2);
                const float y01 = __shfl_sync(0xffffffff, S[kt][1], src2);
                const float y10 = __shfl_sync(0xffffffff, S[kt][2], src2);
                const float y11 = __shfl_sync(0xffffffff, S[kt][3], src2);
                const uint32_t pa0 = f2tf32(hi ? x01 : x00);
                const uint32_t pa1 = f2tf32(hi ? x11 : x10);
                const uint32_t pa2 = f2tf32(hi ? y01 : y00);
                const uint32_t pa3 = f2tf32(hi ? y11 : y10);
                const uint32_t* v0p = Vc + (kt * 8 + lc) * VLD + lr;
                const uint32_t* v1p = Vc + (kt * 8 + lc + 4) * VLD + lr;
                #pragma unroll
                for (int dt = 0; dt < 8; dt++)
                    mma_tf32(O[dt][0], O[dt][1], O[dt][2], O[dt][3],
                             pa0, pa1, pa2, pa3, v0p[dt * 8], v1p[dt * 8]);
            }
        }
    }

    // ---- write output (tf32 pre-rounded for proj GEMM) ----
    if (wid < 13) {
        const float inv0 = v0 ? (1.f / l0) : 0.f;
        const float inv1 = v1 ? (1.f / l1) : 0.f;
        float* o0 = attn + ((size_t)b * NTOK + 1 + fi * NWIN + r0) * DMODEL + h * DHEAD;
        float* o1 = attn + ((size_t)b * NTOK + 1 + fi * NWIN + r1) * DMODEL + h * DHEAD;
        #pragma unroll
        for (int dt = 0; dt < 8; dt++) {
            const int d = dt * 8 + 2 * lc;
            if (v0) *reinterpret_cast<float2*>(o0 + d) = make_float2(
                __uint_as_float(f2tf32(O[dt][0] * inv0)),
                __uint_as_float(f2tf32(O[dt][1] * inv0)));
            if (v1) *reinterpret_cast<float2*>(o1 + d) = make_float2(
                __uint_as_float(f2tf32(O[dt][2] * inv1)),
                __uint_as_float(f2tf32(O[dt][3] * inv1)));
        }
    }
}

// ---------------------------------------------------------------------------
// cls-token attention: one block per (b, h). Output tf32-pre-rounded.
// ---------------------------------------------------------------------------
__global__ __launch_bounds__(256) void cls_attn_kernel(
    const float* __restrict__ qkv, float* __restrict__ attn)
{
    __shared__ float sims[NTOK];
    __shared__ float qs[DHEAD];
    __shared__ float red[256];

    const int bh = blockIdx.x;
    const int h  = bh % NHEAD;
    const int b  = bh / NHEAD;
    const int tid = threadIdx.x;

    const size_t base = (size_t)b * NTOK * QKVCOLS;
    const int qcol = h * DHEAD;
    const int kcol = DMODEL + h * DHEAD;
    const int vcol = 2 * DMODEL + h * DHEAD;

    if (tid < DHEAD) qs[tid] = qkv[base + qcol + tid] * 0.125f;
    __syncthreads();

    for (int j = tid; j < NTOK; j += 256) {
        const float* kp = qkv + base + (size_t)j * QKVCOLS + kcol;
        float s = 0.f;
        #pragma unroll
        for (int d = 0; d < DHEAD; d++) s = fmaf(qs[d], kp[d], s);
        sims[j] = s;
    }
    __syncthreads();

    float m = -1e30f;
    for (int j = tid; j < NTOK; j += 256) m = fmaxf(m, sims[j]);
    red[tid] = m; __syncthreads();
    for (int s2 = 128; s2 > 0; s2 >>= 1) {
        if (tid < s2) red[tid] = fmaxf(red[tid], red[tid + s2]);
        __syncthreads();
    }
    m = red[0]; __syncthreads();

    float lsum = 0.f;
    for (int j = tid; j < NTOK; j += 256) {
        float p = __expf(sims[j] - m);
        sims[j] = p;
        lsum += p;
    }
    red[tid] = lsum; __syncthreads();
    for (int s2 = 128; s2 > 0; s2 >>= 1) {
        if (tid < s2) red[tid] += red[tid + s2];
        __syncthreads();
    }
    float inv = 1.f / red[0];
    __syncthreads();

    const int d  = tid & 63;
    const int jg = tid >> 6;
    float o = 0.f;
    for (int j = jg; j < NTOK; j += 4)
        o = fmaf(sims[j], qkv[base + (size_t)j * QKVCOLS + vcol + d], o);
    red[tid] = o; __syncthreads();
    if (jg == 0) {
        o = red[d] + red[64 + d] + red[128 + d] + red[192 + d];
        attn[(size_t)b * NTOK * DMODEL + h * DHEAD + d] =
            __uint_as_float(f2tf32(o * inv));
    }
}

// ---------------------------------------------------------------------------
extern "C" void kernel_launch(void* const* d_in, const int* in_sizes, int n_in,
                              void* d_out, int out_size)
{
    const float* x      = (const float*)d_in[0];
    const float* w_qkv  = (const float*)d_in[1];
    const float* w_proj = (const float*)d_in[2];
    const float* b_proj = (const float*)d_in[3];
    float* out = (float*)d_out;

    float* qkv   = nullptr;
    float* attn  = nullptr;
    float* xtf   = nullptr;
    float* wqkv  = nullptr;
    float* wproj = nullptr;
    cudaGetSymbolAddress((void**)&qkv,   g_qkv);
    cudaGetSymbolAddress((void**)&attn,  g_attn);
    cudaGetSymbolAddress((void**)&xtf,   g_xtf);
    cudaGetSymbolAddress((void**)&wqkv,  g_wqkv);
    cudaGetSymbolAddress((void**)&wproj, g_wproj);

    cudaFuncSetAttribute(mm_tf32_kernel,
                         cudaFuncAttributeMaxDynamicSharedMemorySize, MM_SMEM);

    // 0) pre-round inputs to tf32
    cvt_tf32_kernel<<<4096, 256>>>(x,      xtf,   MROWS * DMODEL / 4);
    cvt_tf32_kernel<<<1024, 256>>>(w_qkv,  wqkv,  DMODEL * QKVCOLS / 4);
    cvt_tf32_kernel<<<512,  256>>>(w_proj, wproj, DMODEL * DMODEL / 4);

    // 1) qkv = x @ w_qkv   [25104 x 2304]
    {
        dim3 grid(QKVCOLS / 128, (MROWS + 127) / 128);
        mm_tf32_kernel<<<grid, 256, MM_SMEM>>>(xtf, wqkv, qkv, nullptr, MROWS, QKVCOLS);
    }
    // 2) windowed attention (flash, register softmax)
    win_attn_mma_kernel<<<BATCH * NHEAD * NF, 512>>>(qkv, attn);
    // 3) cls attention
    cls_attn_kernel<<<BATCH * NHEAD, 256>>>(qkv, attn);
    // 4) out = attn @ w_proj + b_proj   [25104 x 768]
    {
        dim3 grid(DMODEL / 128, (MROWS + 127) / 128);
        mm_tf32_kernel<<<grid, 256, MM_SMEM>>>(attn, wproj, out, b_proj, MROWS, DMODEL);
    }
}

// round 15
// speedup vs baseline: 4.5227x; 1.4671x over previous
#include <cuda_runtime.h>
#include <cuda_fp16.h>
#include <cuda_bf16.h>
#include <cstdint>

// Problem constants (fixed by setup_inputs)
#define BATCH   16
#define NTOK    1569          // 1 + 8*196
#define DMODEL  768
#define NHEAD   12
#define DHEAD   64
#define NF      8
#define NWIN    196
#define NKEY    197
#define MROWS   (BATCH * NTOK)      // 25104
#define QKVCOLS (3 * DMODEL)        // 2304

// Scratch (allocation-free rule: __device__ globals)
__device__ float  g_qkv  [ (size_t)MROWS * QKVCOLS ];     // fp32 qkv
__device__ __half g_attn [ (size_t)MROWS * DMODEL  ];     // fp16 attn (A of proj)
__device__ __half g_xh   [ (size_t)MROWS * DMODEL  ];     // fp16 x    (A of qkv)
__device__ uint32_t g_wqkv [ (size_t)(DMODEL/2) * QKVCOLS ]; // k-pair half2 words
__device__ uint32_t g_wproj[ (size_t)(DMODEL/2) * DMODEL  ];

__device__ __forceinline__ uint32_t f2tf32(float x) {
    uint32_t r;
    asm("cvt.rna.tf32.f32 %0, %1;" : "=r"(r) : "f"(x));
    return r;
}

__device__ __forceinline__ void mma_tf32(
    float& c0, float& c1, float& c2, float& c3,
    uint32_t a0, uint32_t a1, uint32_t a2, uint32_t a3,
    uint32_t b0, uint32_t b1)
{
    asm volatile(
        "mma.sync.aligned.m16n8k8.row.col.f32.tf32.tf32.f32 "
        "{%0,%1,%2,%3}, {%4,%5,%6,%7}, {%8,%9}, {%0,%1,%2,%3};"
        : "+f"(c0), "+f"(c1), "+f"(c2), "+f"(c3)
        : "r"(a0), "r"(a1), "r"(a2), "r"(a3), "r"(b0), "r"(b1));
}

__device__ __forceinline__ void mma_f16(
    float& c0, float& c1, float& c2, float& c3,
    uint32_t a0, uint32_t a1, uint32_t a2, uint32_t a3,
    uint32_t b0, uint32_t b1)
{
    asm volatile(
        "mma.sync.aligned.m16n8k16.row.col.f32.f16.f16.f32 "
        "{%0,%1,%2,%3}, {%4,%5,%6,%7}, {%8,%9}, {%0,%1,%2,%3};"
        : "+f"(c0), "+f"(c1), "+f"(c2), "+f"(c3)
        : "r"(a0), "r"(a1), "r"(a2), "r"(a3), "r"(b0), "r"(b1));
}

__device__ __forceinline__ void cpa16(uint32_t dst, const void* src, bool pred) {
    int sz = pred ? 16 : 0;
    asm volatile("cp.async.cg.shared.global [%0], [%1], 16, %2;"
                 :: "r"(dst), "l"(src), "r"(sz));
}

// ---------------------------------------------------------------------------
// cvt: fp32 -> fp16 (plain rows, for GEMM A side)
// ---------------------------------------------------------------------------
__global__ __launch_bounds__(256) void cvt_f16_kernel(
    const float* __restrict__ in, __half* __restrict__ out, int n4)
{
    for (int i = blockIdx.x * blockDim.x + threadIdx.x; i < n4;
         i += gridDim.x * blockDim.x) {
        float4 v = reinterpret_cast<const float4*>(in)[i];
        __half2* o = reinterpret_cast<__half2*>(out) + i * 2;
        o[0] = __floats2half2_rn(v.x, v.y);
        o[1] = __floats2half2_rn(v.z, v.w);
    }
}

// ---------------------------------------------------------------------------
// pack: fp32 B[K][N] -> half2 words W[K/2][N], W[kk][n] = (B[2kk][n], B[2kk+1][n])
// ---------------------------------------------------------------------------
__global__ __launch_bounds__(256) void pack_b_kernel(
    const float* __restrict__ B, uint32_t* __restrict__ W, int N, int K2)
{
    const int total = K2 * N;
    for (int i = blockIdx.x * blockDim.x + threadIdx.x; i < total;
         i += gridDim.x * blockDim.x) {
        const int kk = i / N;
        const int n  = i - kk * N;
        __half2 h = __floats2half2_rn(B[(size_t)(2 * kk) * N + n],
                                      B[(size_t)(2 * kk + 1) * N + n]);
        W[i] = *reinterpret_cast<uint32_t*>(&h);
    }
}

// ===========================================================================
// FP16 mma.sync GEMM:  C[M,N] = A[M,768] @ B[768,N] (+bias), fp32 accum.
// A: plain half rows. B: k-pair-interleaved half2 words [384][N].
// CTA 128x128, BK=32 per stage (2 x k16 steps), cp.async 4-stage pipeline.
// A tile: 128 rows x 32 half, row stride 80B (20 words) - conflict-free
// ldmatrix.x4.b16. B tile: 16 pair-rows x 128 words, stride 136 words.
// ===========================================================================
#define GK     768
#define BK     32
#define NC     (GK / BK)       // 24
#define AS_W   (128 * 20)      // 2560 words / stage
#define BS_W   (16 * 136)      // 2176 words / stage
#define STW    (AS_W + BS_W)   // 4736 words / stage
#define STAGES 4
#define MM_SMEM (STAGES * STW * 4)   // 75776 bytes

__global__ __launch_bounds__(256, 2) void mm_f16_kernel(
    const __half* __restrict__ A, const uint32_t* __restrict__ B2,
    float* __restrict__ C, const float* __restrict__ bias, int M, int N)
{
    extern __shared__ float sm[];
    const uint32_t smem_u = (uint32_t)__cvta_generic_to_shared(sm);

    const int tid  = threadIdx.x;
    const int wid  = tid >> 5;
    const int lane = tid & 31;
    const int lr   = lane >> 2;
    const int lc   = lane & 3;
    const int wr   = (wid & 1) * 64;
    const int wc   = (wid >> 1) * 32;
    const int row0 = blockIdx.y * 128;
    const int col0 = blockIdx.x * 128;

    const int arow = wr + (lane & 15);
    const int koff = (lane >> 4) * 4;    // 16B group for ldmatrix (k-half)

    float acc[4][4][4];
    #pragma unroll
    for (int i = 0; i < 4; i++)
        #pragma unroll
        for (int j = 0; j < 4; j++)
            #pragma unroll
            for (int q = 0; q < 4; q++) acc[i][j][q] = 0.f;

    auto issue = [&](int c, int s) {
        const uint32_t ab = smem_u + (uint32_t)(s * STW) * 4u;
        const uint32_t bb = ab + AS_W * 4u;
        const int k0 = c * BK;           // in halves / k units
        #pragma unroll
        for (int t2 = 0; t2 < 2; t2++) {
            const int ida = tid + 256 * t2;
            // A: 512 chunks of 16B (8 halves): m = ida>>2, ch = ida&3
            const int m  = ida >> 2;
            const int ch = ida & 3;
            cpa16(ab + (uint32_t)(m * 80 + ch * 16),
                  A + (size_t)(row0 + m) * GK + k0 + ch * 8,
                  (row0 + m) < M);
            // B: 512 chunks of 16B (4 words): kk = ida>>5 (0..15), cn = ida&31
            const int kk = ida >> 5;
            const int cn = ida & 31;
            cpa16(bb + (uint32_t)(kk * 136 + cn * 4) * 4u,
                  B2 + (size_t)(k0 / 2 + kk) * N + col0 + cn * 4, true);
        }
        asm volatile("cp.async.commit_group;" ::: "memory");
    };

    issue(0, 0); issue(1, 1); issue(2, 2);

    for (int c = 0; c < NC; c++) {
        const int s = c & 3;
        asm volatile("cp.async.wait_group 2;" ::: "memory");
        __syncthreads();
        if (c + 3 < NC) issue(c + 3, (c + 3) & 3);

        const uint32_t ab = smem_u + (uint32_t)(s * STW) * 4u;
        const uint32_t* Bw = reinterpret_cast<const uint32_t*>(sm + s * STW + AS_W);

        #pragma unroll
        for (int ks = 0; ks < 2; ks++) {       // two k16 steps per chunk
            uint32_t af[4][4];
            #pragma unroll
            for (int i = 0; i < 4; i++) {
                const uint32_t addr =
                    ab + (uint32_t)((arow + i * 16) * 20 + ks * 8 + koff) * 4u;
                asm volatile(
                    "ldmatrix.sync.aligned.m8n8.x4.shared.b16 {%0,%1,%2,%3}, [%4];"
                    : "=r"(af[i][0]), "=r"(af[i][1]), "=r"(af[i][2]), "=r"(af[i][3])
                    : "r"(addr));
            }
            uint32_t bf[4][2];
            #pragma unroll
            for (int j = 0; j < 4; j++) {
                const int n = wc + j * 8 + lr;
                bf[j][0] = Bw[(ks * 8 + lc) * 136 + n];
                bf[j][1] = Bw[(ks * 8 + lc + 4) * 136 + n];
            }
            #pragma unroll
            for (int i = 0; i < 4; i++)
                #pragma unroll
                for (int j = 0; j < 4; j++)
                    mma_f16(acc[i][j][0], acc[i][j][1], acc[i][j][2], acc[i][j][3],
                            af[i][0], af[i][1], af[i][2], af[i][3],
                            bf[j][0], bf[j][1]);
        }
    }
    asm volatile("cp.async.wait_group 0;" ::: "memory");

    #pragma unroll
    for (int i = 0; i < 4; i++) {
        const int r = row0 + wr + i * 16 + lr;
        #pragma unroll
        for (int j = 0; j < 4; j++) {
            const int n = col0 + wc + j * 8 + lc * 2;
            float b0 = 0.f, b1 = 0.f;
            if (bias) { b0 = bias[n]; b1 = bias[n + 1]; }
            if (r < M) {
                float2 v = make_float2(acc[i][j][0] + b0, acc[i][j][1] + b1);
                *reinterpret_cast<float2*>(&C[(size_t)r * N + n]) = v;
            }
            if (r + 8 < M) {
                float2 v = make_float2(acc[i][j][2] + b0, acc[i][j][3] + b1);
                *reinterpret_cast<float2*>(&C[(size_t)(r + 8) * N + n]) = v;
            }
        }
    }
}

// ===========================================================================
// Flash-style windowed attention (tf32 mma, register softmax). Unchanged
// except epilogue writes __half to g_attn.
// ===========================================================================
#define KCH  64
#define KLD  68
#define VLD  72

__global__ __launch_bounds__(512, 1) void win_attn_mma_kernel(
    const float* __restrict__ qkv, __half* __restrict__ attn)
{
    __shared__ uint32_t Kc[KCH * KLD];
    __shared__ uint32_t Vc[KCH * VLD];

    const int w  = blockIdx.x;
    const int fi = w % NF;
    const int bh = w / NF;
    const int h  = bh % NHEAD;
    const int b  = bh / NHEAD;
    const int tid  = threadIdx.x;
    const int wid  = tid >> 5;
    const int lane = tid & 31;
    const int lr   = lane >> 2;
    const int lc   = lane & 3;

    const size_t base = (size_t)b * NTOK * QKVCOLS;
    const int qcol = h * DHEAD;
    const int kcol = DMODEL + h * DHEAD;
    const int vcol = 2 * DMODEL + h * DHEAD;

    uint32_t qf[8][4];
    const int r0 = wid * 16 + lr;
    const int r1 = r0 + 8;
    const bool v0 = (wid < 13) && (r0 < NWIN);
    const bool v1 = (wid < 13) && (r1 < NWIN);
    {
        const float* q0 = qkv + base + (size_t)(1 + fi * NWIN + r0) * QKVCOLS + qcol;
        const float* q1 = qkv + base + (size_t)(1 + fi * NWIN + r1) * QKVCOLS + qcol;
        #pragma unroll
        for (int ks = 0; ks < 8; ks++) {
            const int d0 = ks * 8 + lc;
            qf[ks][0] = v0 ? f2tf32(q0[d0]     * 0.125f) : 0u;
            qf[ks][1] = v1 ? f2tf32(q1[d0]     * 0.125f) : 0u;
            qf[ks][2] = v0 ? f2tf32(q0[d0 + 4] * 0.125f) : 0u;
            qf[ks][3] = v1 ? f2tf32(q1[d0 + 4] * 0.125f) : 0u;
        }
    }

    float O[8][4];
    #pragma unroll
    for (int dt = 0; dt < 8; dt++)
        #pragma unroll
        for (int q = 0; q < 4; q++) O[dt][q] = 0.f;
    float m0 = -1e30f, m1 = -1e30f, l0 = 0.f, l1 = 0.f;

    const int src1 = lr * 4 + (lc >> 1);
    const int src2 = src1 + 2;
    const bool hi  = lc & 1;

    #pragma unroll 1
    for (int c = 0; c < 4; c++) {
        const int kb0 = c * KCH;
        const int len = min(KCH, NKEY - kb0);
        const int NT  = (len + 7) >> 3;

        __syncthreads();
        for (int idx = tid; idx < KCH * 16; idx += 512) {
            const int kr = idx >> 4;
            const int d4 = (idx & 15) * 4;
            const int gk = kb0 + kr;
            float4 kv = make_float4(0.f, 0.f, 0.f, 0.f), vv = kv;
            if (gk < NKEY) {
                const int tok = (gk == 0) ? 0 : (1 + fi * NWIN + (gk - 1));
                const float* rp = qkv + base + (size_t)tok * QKVCOLS;
                kv = *reinterpret_cast<const float4*>(rp + kcol + d4);
                vv = *reinterpret_cast<const float4*>(rp + vcol + d4);
            }
            uint32_t* kp = Kc + kr * KLD + d4;
            kp[0] = f2tf32(kv.x); kp[1] = f2tf32(kv.y);
            kp[2] = f2tf32(kv.z); kp[3] = f2tf32(kv.w);
            uint32_t* vp = Vc + kr * VLD + d4;
            vp[0] = f2tf32(vv.x); vp[1] = f2tf32(vv.y);
            vp[2] = f2tf32(vv.z); vp[3] = f2tf32(vv.w);
        }
        __syncthreads();

        if (wid < 13) {
            float S[8][4];
            #pragma unroll
            for (int nt = 0; nt < 8; nt++) {
                if (nt >= NT) break;
                float a0 = 0.f, a1 = 0.f, a2 = 0.f, a3 = 0.f;
                const uint32_t* kp = Kc + (nt * 8 + lr) * KLD + lc;
                #pragma unroll
                for (int ks = 0; ks < 8; ks++)
                    mma_tf32(a0, a1, a2, a3,
                             qf[ks][0], qf[ks][1], qf[ks][2], qf[ks][3],
                             kp[ks * 8], kp[ks * 8 + 4]);
                S[nt][0] = a0; S[nt][1] = a1; S[nt][2] = a2; S[nt][3] = a3;
            }

            if (len < KCH) {
                #pragma unroll
                for (int nt = 0; nt < 8; nt++) {
                    if (nt >= NT) break;
                    const int cc = nt * 8 + 2 * lc;
                    if (cc     >= len) { S[nt][0] = -1e30f; S[nt][2] = -1e30f; }
                    if (cc + 1 >= len) { S[nt][1] = -1e30f; S[nt][3] = -1e30f; }
                }
            }

            float cm0 = -1e30f, cm1 = -1e30f;
            #pragma unroll
            for (int nt = 0; nt < 8; nt++) {
                if (nt >= NT) break;
                cm0 = fmaxf(cm0, fmaxf(S[nt][0], S[nt][1]));
                cm1 = fmaxf(cm1, fmaxf(S[nt][2], S[nt][3]));
            }
            cm0 = fmaxf(cm0, __shfl_xor_sync(0xffffffff, cm0, 1));
            cm0 = fmaxf(cm0, __shfl_xor_sync(0xffffffff, cm0, 2));
            cm1 = fmaxf(cm1, __shfl_xor_sync(0xffffffff, cm1, 1));
            cm1 = fmaxf(cm1, __shfl_xor_sync(0xffffffff, cm1, 2));
            const float nm0 = fmaxf(m0, cm0);
            const float nm1 = fmaxf(m1, cm1);
            const float f0 = __expf(m0 - nm0);
            const float f1 = __expf(m1 - nm1);
            m0 = nm0; m1 = nm1;

            float cl0 = 0.f, cl1 = 0.f;
            #pragma unroll
            for (int nt = 0; nt < 8; nt++) {
                if (nt >= NT) break;
                S[nt][0] = __expf(S[nt][0] - m0);
                S[nt][1] = __expf(S[nt][1] - m0);
                S[nt][2] = __expf(S[nt][2] - m1);
                S[nt][3] = __expf(S[nt][3] - m1);
                cl0 += S[nt][0] + S[nt][1];
                cl1 += S[nt][2] + S[nt][3];
            }
            cl0 += __shfl_xor_sync(0xffffffff, cl0, 1);
            cl0 += __shfl_xor_sync(0xffffffff, cl0, 2);
            cl1 += __shfl_xor_sync(0xffffffff, cl1, 1);
            cl1 += __shfl_xor_sync(0xffffffff, cl1, 2);
            l0 = l0 * f0 + cl0;
            l1 = l1 * f1 + cl1;

            #pragma unroll
            for (int dt = 0; dt < 8; dt++) {
                O[dt][0] *= f0; O[dt][1] *= f0;
                O[dt][2] *= f1; O[dt][3] *= f1;
            }

            #pragma unroll
            for (int kt = 0; kt < 8; kt++) {
                if (kt >= NT) break;
                const float x00 = __shfl_sync(0xffffffff, S[kt][0], src1);
                const float x01 = __shfl_sync(0xffffffff, S[kt][1], src1);
                const float x10 = __shfl_sync(0xffffffff, S[kt][2], src1);
                const float x11 = __shfl_sync(0xffffffff, S[kt][3], src1);
                const float y00 = __shfl_sync(0xffffffff, S[kt][0], src2);
                const float y01 = __shfl_sync(0xffffffff, S[kt][1], src2);
                const float y10 = __shfl_sync(0xffffffff, S[kt][2], src2);
                const float y11 = __shfl_sync(0xffffffff, S[kt][3], src2);
                const uint32_t pa0 = f2tf32(hi ? x01 : x00);
                const uint32_t pa1 = f2tf32(hi ? x11 : x10);
                const uint32_t pa2 = f2tf32(hi ? y01 : y00);
                const uint32_t pa3 = f2tf32(hi ? y11 : y10);
                const uint32_t* v0p = Vc + (kt * 8 + lc) * VLD + lr;
                const uint32_t* v1p = Vc + (kt * 8 + lc + 4) * VLD + lr;
                #pragma unroll
                for (int dt = 0; dt < 8; dt++)
                    mma_tf32(O[dt][0], O[dt][1], O[dt][2], O[dt][3],
                             pa0, pa1, pa2, pa3, v0p[dt * 8], v1p[dt * 8]);
            }
        }
    }

    if (wid < 13) {
        const float inv0 = v0 ? (1.f / l0) : 0.f;
        const float inv1 = v1 ? (1.f / l1) : 0.f;
        __half* o0 = attn + ((size_t)b * NTOK + 1 + fi * NWIN + r0) * DMODEL + h * DHEAD;
        __half* o1 = attn + ((size_t)b * NTOK + 1 + fi * NWIN + r1) * DMODEL + h * DHEAD;
        #pragma unroll
        for (int dt = 0; dt < 8; dt++) {
            const int d = dt * 8 + 2 * lc;
            if (v0) *reinterpret_cast<__half2*>(o0 + d) =
                __floats2half2_rn(O[dt][0] * inv0, O[dt][1] * inv0);
            if (v1) *reinterpret_cast<__half2*>(o1 + d) =
                __floats2half2_rn(O[dt][2] * inv1, O[dt][3] * inv1);
        }
    }
}

// ---------------------------------------------------------------------------
// cls-token attention: one block per (b, h). Writes __half.
// ---------------------------------------------------------------------------
__global__ __launch_bounds__(256) void cls_attn_kernel(
    const float* __restrict__ qkv, __half* __restrict__ attn)
{
    __shared__ float sims[NTOK];
    __shared__ float qs[DHEAD];
    __shared__ float red[256];

    const int bh = blockIdx.x;
    const int h  = bh % NHEAD;
    const int b  = bh / NHEAD;
    const int tid = threadIdx.x;

    const size_t base = (size_t)b * NTOK * QKVCOLS;
    const int qcol = h * DHEAD;
    const int kcol = DMODEL + h * DHEAD;
    const int vcol = 2 * DMODEL + h * DHEAD;

    if (tid < DHEAD) qs[tid] = qkv[base + qcol + tid] * 0.125f;
    __syncthreads();

    for (int j = tid; j < NTOK; j += 256) {
        const float* kp = qkv + base + (size_t)j * QKVCOLS + kcol;
        float s = 0.f;
        #pragma unroll
        for (int d = 0; d < DHEAD; d++) s = fmaf(qs[d], kp[d], s);
        sims[j] = s;
    }
    __syncthreads();

    float m = -1e30f;
    for (int j = tid; j < NTOK; j += 256) m = fmaxf(m, sims[j]);
    red[tid] = m; __syncthreads();
    for (int s2 = 128; s2 > 0; s2 >>= 1) {
        if (tid < s2) red[tid] = fmaxf(red[tid], red[tid + s2]);
        __syncthreads();
    }
    m = red[0]; __syncthreads();

    float lsum = 0.f;
    for (int j = tid; j < NTOK; j += 256) {
        float p = __expf(sims[j] - m);
        sims[j] = p;
        lsum += p;
    }
    red[tid] = lsum; __syncthreads();
    for (int s2 = 128; s2 > 0; s2 >>= 1) {
        if (tid < s2) red[tid] += red[tid + s2];
        __syncthreads();
    }
    float inv = 1.f / red[0];
    __syncthreads();

    const int d  = tid & 63;
    const int jg = tid >> 6;
    float o = 0.f;
    for (int j = jg; j < NTOK; j += 4)
        o = fmaf(sims[j], qkv[base + (size_t)j * QKVCOLS + vcol + d], o);
    red[tid] = o; __syncthreads();
    if (jg == 0) {
        o = red[d] + red[64 + d] + red[128 + d] + red[192 + d];
        attn[(size_t)b * NTOK * DMODEL + h * DHEAD + d] = __float2half(o * inv);
    }
}

// ---------------------------------------------------------------------------
extern "C" void kernel_launch(void* const* d_in, const int* in_sizes, int n_in,
                              void* d_out, int out_size)
{
    const float* x      = (const float*)d_in[0];
    const float* w_qkv  = (const float*)d_in[1];
    const float* w_proj = (const float*)d_in[2];
    const float* b_proj = (const float*)d_in[3];
    float* out = (float*)d_out;

    float*    qkv   = nullptr;
    __half*   attn  = nullptr;
    __half*   xh    = nullptr;
    uint32_t* wqkv  = nullptr;
    uint32_t* wproj = nullptr;
    cudaGetSymbolAddress((void**)&qkv,   g_qkv);
    cudaGetSymbolAddress((void**)&attn,  g_attn);
    cudaGetSymbolAddress((void**)&xh,    g_xh);
    cudaGetSymbolAddress((void**)&wqkv,  g_wqkv);
    cudaGetSymbolAddress((void**)&wproj, g_wproj);

    cudaFuncSetAttribute(mm_f16_kernel,
                         cudaFuncAttributeMaxDynamicSharedMemorySize, MM_SMEM);

    // 0) convert/pack inputs
    cvt_f16_kernel<<<4096, 256>>>(x, xh, MROWS * DMODEL / 4);
    pack_b_kernel<<<2048, 256>>>(w_qkv,  wqkv,  QKVCOLS, DMODEL / 2);
    pack_b_kernel<<<1024, 256>>>(w_proj, wproj, DMODEL,  DMODEL / 2);

    // 1) qkv = x @ w_qkv   [25104 x 2304]
    {
        dim3 grid(QKVCOLS / 128, (MROWS + 127) / 128);
        mm_f16_kernel<<<grid, 256, MM_SMEM>>>(xh, wqkv, qkv, nullptr, MROWS, QKVCOLS);
    }
    // 2) windowed attention (flash, register softmax)
    win_attn_mma_kernel<<<BATCH * NHEAD * NF, 512>>>(qkv, attn);
    // 3) cls attention
    cls_attn_kernel<<<BATCH * NHEAD, 256>>>(qkv, attn);
    // 4) out = attn @ w_proj + b_proj   [25104 x 768]
    {
        dim3 grid(DMODEL / 128, (MROWS + 127) / 128);
        mm_f16_kernel<<<grid, 256, MM_SMEM>>>(attn, wproj, out, b_proj, MROWS, DMODEL);
    }
}